// round 1
// baseline (speedup 1.0000x reference)
#include <cuda_runtime.h>
#include <cuda_bf16.h>
#include <math.h>

// Problem constants
#define BB   2
#define TT   2048
#define CC   2048
#define NH   16
#define HD   128
#define MM   (BB*TT)        // 4096
#define N_QKV (3*CC)        // 6144

// ---------------------------------------------------------------------------
// Scratch (device globals; no runtime allocation)
// ---------------------------------------------------------------------------
__device__ float g_q[(size_t)BB*NH*TT*HD];   // [B,H,T,hd]
__device__ float g_k[(size_t)BB*NH*TT*HD];
__device__ float g_v[(size_t)BB*NH*TT*HD];
__device__ float g_y[(size_t)BB*TT*CC];      // attention output [B,T,C]

// ---------------------------------------------------------------------------
// SGEMM: C = A[M,K] @ B[K,N].  128x128 block tile, BK=8, 256 thr, 8x8/thread.
// MODE 0: A = param, epilogue scatters into g_q/g_k/g_v (head-major)
// MODE 1: A = g_y,   epilogue writes plain row-major C (d_out)
// ---------------------------------------------------------------------------
template <int MODE>
__global__ void __launch_bounds__(256)
sgemm_kernel(const float* __restrict__ Ap, const float* __restrict__ Bp,
             float* __restrict__ Cp, int M, int N, int K)
{
    __shared__ float As[8][128];
    __shared__ float Bs[8][128];

    const float* A = (MODE == 0) ? Ap : (const float*)g_y;

    int bx = blockIdx.x;   // N tile
    int by = blockIdx.y;   // M tile
    int tid = threadIdx.x;
    int tx = tid & 15;     // 0..15
    int ty = tid >> 4;     // 0..15

    // A tile load indices: 128 rows x 2 float4
    int a_row = tid >> 1;          // 0..127
    int a_c4  = (tid & 1) * 4;     // 0 or 4
    // B tile load indices: 8 rows x 32 float4
    int b_row = tid >> 5;          // 0..7
    int b_c4  = (tid & 31) * 4;    // 0..124

    float acc[8][8];
#pragma unroll
    for (int i = 0; i < 8; i++)
#pragma unroll
        for (int j = 0; j < 8; j++) acc[i][j] = 0.f;

    for (int k0 = 0; k0 < K; k0 += 8) {
        // load A tile (transpose into As[kk][m])
        float4 av = *(const float4*)(A + (size_t)(by*128 + a_row)*K + k0 + a_c4);
        As[a_c4 + 0][a_row] = av.x;
        As[a_c4 + 1][a_row] = av.y;
        As[a_c4 + 2][a_row] = av.z;
        As[a_c4 + 3][a_row] = av.w;
        // load B tile
        float4 bv = *(const float4*)(Bp + (size_t)(k0 + b_row)*N + bx*128 + b_c4);
        *(float4*)(&Bs[b_row][b_c4]) = bv;
        __syncthreads();

#pragma unroll
        for (int kk = 0; kk < 8; kk++) {
            float4 a0 = *(float4*)(&As[kk][ty*8]);
            float4 a1 = *(float4*)(&As[kk][ty*8 + 4]);
            float4 b0 = *(float4*)(&Bs[kk][tx*8]);
            float4 b1 = *(float4*)(&Bs[kk][tx*8 + 4]);
            float a[8] = {a0.x,a0.y,a0.z,a0.w,a1.x,a1.y,a1.z,a1.w};
            float b[8] = {b0.x,b0.y,b0.z,b0.w,b1.x,b1.y,b1.z,b1.w};
#pragma unroll
            for (int i = 0; i < 8; i++)
#pragma unroll
                for (int j = 0; j < 8; j++)
                    acc[i][j] = fmaf(a[i], b[j], acc[i][j]);
        }
        __syncthreads();
    }

    if (MODE == 0) {
        // scatter into q/k/v head-major scratch
#pragma unroll
        for (int i = 0; i < 8; i++) {
            int m = by*128 + ty*8 + i;
            int bb = m >> 11;          // /2048
            int t  = m & 2047;
#pragma unroll
            for (int j = 0; j < 8; j++) {
                int n = bx*128 + tx*8 + j;
                int which = n >> 11;
                int c = n & 2047;
                int h = c >> 7;
                int dd = c & 127;
                size_t dst = ((size_t)(bb*NH + h)*TT + t)*HD + dd;
                float v = acc[i][j];
                if (which == 0)      g_q[dst] = v;
                else if (which == 1) g_k[dst] = v;
                else                 g_v[dst] = v;
            }
        }
    } else {
#pragma unroll
        for (int i = 0; i < 8; i++) {
            int m = by*128 + ty*8 + i;
#pragma unroll
            for (int j = 0; j < 8; j++) {
                int n = bx*128 + tx*8 + j;
                Cp[(size_t)m*N + n] = acc[i][j];
            }
        }
    }
}

// ---------------------------------------------------------------------------
// RoPE kernel, applied in place to g_q and g_k.
// grid = B*H*T blocks, 128 threads: threads [0,64) -> q, [64,128) -> k.
// ---------------------------------------------------------------------------
__global__ void rope_kernel(const float* __restrict__ cosp,
                            const float* __restrict__ sinp)
{
    int row = blockIdx.x;            // (b*H + h)*T + t
    int t = row & (TT - 1);
    int tid = threadIdx.x;
    int d = tid & 63;
    float* arr = (tid < 64) ? g_q : g_k;
    float* base = arr + (size_t)row * HD;
    float c = cosp[t*64 + d];
    float s = sinp[t*64 + d];
    float x1 = base[d];
    float x2 = base[d + 64];
    base[d]      = x1*c - x2*s;
    base[d + 64] = x1*s + x2*c;
}

// ---------------------------------------------------------------------------
// Flash attention: Br=Bc=64, d=128, fp32 online softmax.
// grid: (T/64, B*H); 256 threads.  acc per thread: 4 rows x 8 cols.
// ---------------------------------------------------------------------------
#define QS 132   // padded row stride for Q/K/V tiles
#define PS 68    // padded row stride for P tile
#define FLASH_SMEM ((3*64*QS + 64*PS) * sizeof(float))   // 118784 B

__global__ void __launch_bounds__(256)
flash_kernel()
{
    extern __shared__ float sm[];
    float* sQ = sm;
    float* sK = sQ + 64*QS;
    float* sV = sK + 64*QS;
    float* sP = sV + 64*QS;

    int qt  = blockIdx.x;       // query tile
    int bh  = blockIdx.y;       // b*H + h
    int tid = threadIdx.x;
    int tx = tid & 15;
    int ty = tid >> 4;

    // load Q tile
    {
        const float* Qg = g_q + ((size_t)bh*TT + qt*64)*HD;
#pragma unroll
        for (int i = 0; i < 8; i++) {
            int lin = tid + i*256;       // float4 index, 0..2047
            int r = lin >> 5;
            int c4 = (lin & 31) * 4;
            *(float4*)(sQ + r*QS + c4) = *(const float4*)(Qg + r*HD + c4);
        }
    }

    float m_i[4], l_i[4], acc[4][8];
#pragma unroll
    for (int i = 0; i < 4; i++) {
        m_i[i] = -INFINITY; l_i[i] = 0.f;
#pragma unroll
        for (int c = 0; c < 8; c++) acc[i][c] = 0.f;
    }

    const float scale = 0.08838834764831845f;   // 1/sqrt(128)

    for (int jc = 0; jc <= qt; jc++) {
        // load K, V tiles
        const float* Kg = g_k + ((size_t)bh*TT + jc*64)*HD;
        const float* Vg = g_v + ((size_t)bh*TT + jc*64)*HD;
#pragma unroll
        for (int i = 0; i < 8; i++) {
            int lin = tid + i*256;
            int r = lin >> 5;
            int c4 = (lin & 31) * 4;
            *(float4*)(sK + r*QS + c4) = *(const float4*)(Kg + r*HD + c4);
            *(float4*)(sV + r*QS + c4) = *(const float4*)(Vg + r*HD + c4);
        }
        __syncthreads();

        // S = Q @ K^T  (4x4 micro-tile per thread)
        float s[4][4];
#pragma unroll
        for (int i = 0; i < 4; i++)
#pragma unroll
            for (int j = 0; j < 4; j++) s[i][j] = 0.f;

        for (int d = 0; d < 128; d += 4) {
            float4 a[4], b[4];
#pragma unroll
            for (int ii = 0; ii < 4; ii++)
                a[ii] = *(float4*)(sQ + (ty*4 + ii)*QS + d);
#pragma unroll
            for (int jj = 0; jj < 4; jj++)
                b[jj] = *(float4*)(sK + (tx*4 + jj)*QS + d);
#pragma unroll
            for (int ii = 0; ii < 4; ii++)
#pragma unroll
                for (int jj = 0; jj < 4; jj++) {
                    s[ii][jj] = fmaf(a[ii].x, b[jj].x, s[ii][jj]);
                    s[ii][jj] = fmaf(a[ii].y, b[jj].y, s[ii][jj]);
                    s[ii][jj] = fmaf(a[ii].z, b[jj].z, s[ii][jj]);
                    s[ii][jj] = fmaf(a[ii].w, b[jj].w, s[ii][jj]);
                }
        }

        // online softmax per row
#pragma unroll
        for (int ii = 0; ii < 4; ii++) {
            int qrow = qt*64 + ty*4 + ii;
            float rowmax = -INFINITY;
#pragma unroll
            for (int jj = 0; jj < 4; jj++) {
                float sv = s[ii][jj] * scale;
                if (jc == qt && (jc*64 + tx*4 + jj) > qrow) sv = -INFINITY;
                s[ii][jj] = sv;
                rowmax = fmaxf(rowmax, sv);
            }
#pragma unroll
            for (int off = 8; off; off >>= 1)
                rowmax = fmaxf(rowmax, __shfl_xor_sync(0xffffffffu, rowmax, off));

            float m_new = fmaxf(m_i[ii], rowmax);
            float fac = __expf(m_i[ii] - m_new);
            float rsum = 0.f;
#pragma unroll
            for (int jj = 0; jj < 4; jj++) {
                float p = __expf(s[ii][jj] - m_new);
                s[ii][jj] = p;
                rsum += p;
            }
#pragma unroll
            for (int off = 8; off; off >>= 1)
                rsum += __shfl_xor_sync(0xffffffffu, rsum, off);

            l_i[ii] = l_i[ii]*fac + rsum;
            m_i[ii] = m_new;
#pragma unroll
            for (int cc = 0; cc < 8; cc++) acc[ii][cc] *= fac;
#pragma unroll
            for (int jj = 0; jj < 4; jj++)
                sP[(ty*4 + ii)*PS + tx*4 + jj] = s[ii][jj];
        }
        __syncthreads();

        // O += P @ V
        for (int j = 0; j < 64; j++) {
            float p0 = sP[(ty*4 + 0)*PS + j];
            float p1 = sP[(ty*4 + 1)*PS + j];
            float p2 = sP[(ty*4 + 2)*PS + j];
            float p3 = sP[(ty*4 + 3)*PS + j];
            float4 v0 = *(float4*)(sV + j*QS + tx*8);
            float4 v1 = *(float4*)(sV + j*QS + tx*8 + 4);
            float vv[8] = {v0.x,v0.y,v0.z,v0.w,v1.x,v1.y,v1.z,v1.w};
#pragma unroll
            for (int cc = 0; cc < 8; cc++) {
                acc[0][cc] = fmaf(p0, vv[cc], acc[0][cc]);
                acc[1][cc] = fmaf(p1, vv[cc], acc[1][cc]);
                acc[2][cc] = fmaf(p2, vv[cc], acc[2][cc]);
                acc[3][cc] = fmaf(p3, vv[cc], acc[3][cc]);
            }
        }
        __syncthreads();
    }

    // write y [B,T,C]
    int b = bh >> 4;
    int h = bh & 15;
#pragma unroll
    for (int ii = 0; ii < 4; ii++) {
        int t = qt*64 + ty*4 + ii;
        float inv = 1.f / l_i[ii];
        float* yrow = g_y + ((size_t)(b*TT + t))*CC + h*HD + tx*8;
#pragma unroll
        for (int cc = 0; cc < 8; cc++)
            yrow[cc] = acc[ii][cc] * inv;
    }
}

// ---------------------------------------------------------------------------
// launch
// ---------------------------------------------------------------------------
extern "C" void kernel_launch(void* const* d_in, const int* in_sizes, int n_in,
                              void* d_out, int out_size)
{
    const float* x    = (const float*)d_in[0];
    const float* cosp = (const float*)d_in[1];
    const float* sinp = (const float*)d_in[2];
    const float* Wa   = (const float*)d_in[3];
    const float* Wp   = (const float*)d_in[4];
    float* out = (float*)d_out;

    // 1) qkv = x @ W_attn, scattered into head-major q/k/v
    sgemm_kernel<0><<<dim3(N_QKV/128, MM/128), 256>>>(x, Wa, nullptr, MM, N_QKV, CC);

    // 2) RoPE on q,k
    rope_kernel<<<BB*NH*TT, 128>>>(cosp, sinp);

    // 3) flash attention -> g_y
    cudaFuncSetAttribute(flash_kernel, cudaFuncAttributeMaxDynamicSharedMemorySize,
                         (int)FLASH_SMEM);
    flash_kernel<<<dim3(TT/64, BB*NH), 256, FLASH_SMEM>>>();

    // 4) out = y @ W_proj
    sgemm_kernel<1><<<dim3(CC/128, MM/128), 256>>>(nullptr, Wp, out, MM, CC, CC);
}

// round 2
// speedup vs baseline: 2.8272x; 2.8272x over previous
#include <cuda_runtime.h>
#include <cuda_bf16.h>
#include <math.h>

// Problem constants
#define BB   2
#define TT   2048
#define CC   2048
#define NH   16
#define HD   128
#define MM   (BB*TT)        // 4096
#define N_QKV (3*CC)        // 6144

// ---------------------------------------------------------------------------
// Scratch (device globals; no runtime allocation)
// ---------------------------------------------------------------------------
__device__ float g_q[(size_t)BB*NH*TT*HD];   // [B,H,T,hd]
__device__ float g_k[(size_t)BB*NH*TT*HD];
__device__ float g_v[(size_t)BB*NH*TT*HD];
__device__ float g_y[(size_t)BB*TT*CC];      // attention output [B,T,C]

// ---------------------------------------------------------------------------
// TF32 helpers
// ---------------------------------------------------------------------------
__device__ __forceinline__ unsigned f2tf(float x) {
    unsigned r;
    asm("cvt.rna.tf32.f32 %0, %1;" : "=r"(r) : "f"(x));
    return r;
}

__device__ __forceinline__ void mma_tf32(float* c, const unsigned* a, const unsigned* b) {
    asm volatile(
        "mma.sync.aligned.m16n8k8.row.col.f32.tf32.tf32.f32 "
        "{%0,%1,%2,%3}, {%4,%5,%6,%7}, {%8,%9}, {%0,%1,%2,%3};"
        : "+f"(c[0]), "+f"(c[1]), "+f"(c[2]), "+f"(c[3])
        : "r"(a[0]), "r"(a[1]), "r"(a[2]), "r"(a[3]),
          "r"(b[0]), "r"(b[1]));
}

// ---------------------------------------------------------------------------
// TF32 tensor-core GEMM: C = A[M,K] @ B[K,N]
// 128x128 tile, BK=16, double-buffered, 256 threads, 8 warps (4M x 2N),
// warp tile 32x64 (2 m-tiles x 8 n-tiles of m16n8k8).
// MODE 0: A = param, epilogue scatters into g_q/g_k/g_v (head-major)
// MODE 1: A = g_y,   epilogue writes plain row-major C
// ---------------------------------------------------------------------------
#define ASTR 20    // As row stride (words). (lane/4)*20 + lane%4 -> 32 distinct banks
#define BSTR 136   // Bs row stride (words). (lane%4)*136 + lane/4 -> 32 distinct banks

template <int MODE>
__global__ void __launch_bounds__(256)
gemm_tf32(const float* __restrict__ Ap, const float* __restrict__ Bp,
          float* __restrict__ Cp, int M, int N, int K)
{
    __shared__ unsigned As[2][128][ASTR];
    __shared__ unsigned Bs[2][16][BSTR];

    const float* A = (MODE == 0) ? Ap : (const float*)g_y;

    const int bx = blockIdx.x;
    const int by = blockIdx.y;
    const int tid  = threadIdx.x;
    const int lane = tid & 31;
    const int warp = tid >> 5;
    const int wm = warp >> 1;      // 0..3
    const int wn = warp & 1;       // 0..1
    const int tig = lane & 3;      // thread in group
    const int grp = lane >> 2;     // group id

    // global load indexing
    const int a_row = tid >> 2;          // 0..63 (and +64)
    const int a_kc  = (tid & 3) * 4;     // 0,4,8,12
    const int b_k   = tid >> 5;          // 0..7 (and +8)
    const int b_n4  = (tid & 31) * 4;    // 0..124

    const float* Abase = A  + (size_t)(by * 128) * K;
    const float* Bbase = Bp + bx * 128;

    float acc[2][8][4];
#pragma unroll
    for (int i = 0; i < 2; i++)
#pragma unroll
        for (int j = 0; j < 8; j++)
#pragma unroll
            for (int r = 0; r < 4; r++) acc[i][j][r] = 0.f;

    float4 pa0, pa1, pb0, pb1;

    // prologue: load k-step 0
    pa0 = *(const float4*)(Abase + (size_t)a_row * K + a_kc);
    pa1 = *(const float4*)(Abase + (size_t)(a_row + 64) * K + a_kc);
    pb0 = *(const float4*)(Bbase + (size_t)b_k * N + b_n4);
    pb1 = *(const float4*)(Bbase + (size_t)(b_k + 8) * N + b_n4);
    {
        uint4 u;
        u.x = f2tf(pa0.x); u.y = f2tf(pa0.y); u.z = f2tf(pa0.z); u.w = f2tf(pa0.w);
        *(uint4*)&As[0][a_row][a_kc] = u;
        u.x = f2tf(pa1.x); u.y = f2tf(pa1.y); u.z = f2tf(pa1.z); u.w = f2tf(pa1.w);
        *(uint4*)&As[0][a_row + 64][a_kc] = u;
        u.x = f2tf(pb0.x); u.y = f2tf(pb0.y); u.z = f2tf(pb0.z); u.w = f2tf(pb0.w);
        *(uint4*)&Bs[0][b_k][b_n4] = u;
        u.x = f2tf(pb1.x); u.y = f2tf(pb1.y); u.z = f2tf(pb1.z); u.w = f2tf(pb1.w);
        *(uint4*)&Bs[0][b_k + 8][b_n4] = u;
    }
    __syncthreads();

    const int nk = K >> 4;   // K/16
    for (int ks = 0; ks < nk; ks++) {
        const int s = ks & 1;

        // prefetch next k-step from global
        if (ks + 1 < nk) {
            const int k0 = (ks + 1) << 4;
            pa0 = *(const float4*)(Abase + (size_t)a_row * K + k0 + a_kc);
            pa1 = *(const float4*)(Abase + (size_t)(a_row + 64) * K + k0 + a_kc);
            pb0 = *(const float4*)(Bbase + (size_t)(k0 + b_k) * N + b_n4);
            pb1 = *(const float4*)(Bbase + (size_t)(k0 + b_k + 8) * N + b_n4);
        }

        // compute on stage s: 2 k-chunks of 8
#pragma unroll
        for (int kk = 0; kk < 2; kk++) {
            const int kb = kk * 8;
            unsigned af[2][4], bf[8][2];
#pragma unroll
            for (int mt = 0; mt < 2; mt++) {
                const int mr = wm * 32 + mt * 16 + grp;
                af[mt][0] = As[s][mr][kb + tig];
                af[mt][1] = As[s][mr + 8][kb + tig];
                af[mt][2] = As[s][mr][kb + tig + 4];
                af[mt][3] = As[s][mr + 8][kb + tig + 4];
            }
#pragma unroll
            for (int nt = 0; nt < 8; nt++) {
                const int nc = wn * 64 + nt * 8 + grp;
                bf[nt][0] = Bs[s][kb + tig][nc];
                bf[nt][1] = Bs[s][kb + tig + 4][nc];
            }
#pragma unroll
            for (int mt = 0; mt < 2; mt++)
#pragma unroll
                for (int nt = 0; nt < 8; nt++)
                    mma_tf32(acc[mt][nt], af[mt], bf[nt]);
        }

        // store prefetched data into the other stage
        if (ks + 1 < nk) {
            const int so = (ks + 1) & 1;
            uint4 u;
            u.x = f2tf(pa0.x); u.y = f2tf(pa0.y); u.z = f2tf(pa0.z); u.w = f2tf(pa0.w);
            *(uint4*)&As[so][a_row][a_kc] = u;
            u.x = f2tf(pa1.x); u.y = f2tf(pa1.y); u.z = f2tf(pa1.z); u.w = f2tf(pa1.w);
            *(uint4*)&As[so][a_row + 64][a_kc] = u;
            u.x = f2tf(pb0.x); u.y = f2tf(pb0.y); u.z = f2tf(pb0.z); u.w = f2tf(pb0.w);
            *(uint4*)&Bs[so][b_k][b_n4] = u;
            u.x = f2tf(pb1.x); u.y = f2tf(pb1.y); u.z = f2tf(pb1.z); u.w = f2tf(pb1.w);
            *(uint4*)&Bs[so][b_k + 8][b_n4] = u;
        }
        __syncthreads();
    }

    // epilogue
#pragma unroll
    for (int mt = 0; mt < 2; mt++) {
        const int row0 = by * 128 + wm * 32 + mt * 16 + grp;
#pragma unroll
        for (int nt = 0; nt < 8; nt++) {
            const int col = bx * 128 + wn * 64 + nt * 8 + tig * 2;
            if (MODE == 0) {
#pragma unroll
                for (int half = 0; half < 2; half++) {
                    const int row = row0 + half * 8;
                    const int bb = row >> 11;
                    const int t  = row & 2047;
                    const int which = col >> 11;
                    const int c = col & 2047;
                    const int h = c >> 7;
                    const int dd = c & 127;
                    float* base = (which == 0) ? g_q : (which == 1) ? g_k : g_v;
                    float* dst = base + ((size_t)(bb * NH + h) * TT + t) * HD + dd;
                    *(float2*)dst = make_float2(acc[mt][nt][half * 2],
                                                acc[mt][nt][half * 2 + 1]);
                }
            } else {
                *(float2*)(Cp + (size_t)row0 * N + col) =
                    make_float2(acc[mt][nt][0], acc[mt][nt][1]);
                *(float2*)(Cp + (size_t)(row0 + 8) * N + col) =
                    make_float2(acc[mt][nt][2], acc[mt][nt][3]);
            }
        }
    }
}

// ---------------------------------------------------------------------------
// RoPE kernel, applied in place to g_q and g_k.
// ---------------------------------------------------------------------------
__global__ void rope_kernel(const float* __restrict__ cosp,
                            const float* __restrict__ sinp)
{
    int row = blockIdx.x;            // (b*H + h)*T + t
    int t = row & (TT - 1);
    int tid = threadIdx.x;
    int d = tid & 63;
    float* arr = (tid < 64) ? g_q : g_k;
    float* base = arr + (size_t)row * HD;
    float c = cosp[t*64 + d];
    float s = sinp[t*64 + d];
    float x1 = base[d];
    float x2 = base[d + 64];
    base[d]      = x1*c - x2*s;
    base[d + 64] = x1*s + x2*c;
}

// ---------------------------------------------------------------------------
// Flash attention: Br=Bc=64, d=128, fp32 online softmax. (unchanged)
// ---------------------------------------------------------------------------
#define QS 132
#define PS 68
#define FLASH_SMEM ((3*64*QS + 64*PS) * sizeof(float))

__global__ void __launch_bounds__(256)
flash_kernel()
{
    extern __shared__ float sm[];
    float* sQ = sm;
    float* sK = sQ + 64*QS;
    float* sV = sK + 64*QS;
    float* sP = sV + 64*QS;

    int qt  = blockIdx.x;
    int bh  = blockIdx.y;
    int tid = threadIdx.x;
    int tx = tid & 15;
    int ty = tid >> 4;

    {
        const float* Qg = g_q + ((size_t)bh*TT + qt*64)*HD;
#pragma unroll
        for (int i = 0; i < 8; i++) {
            int lin = tid + i*256;
            int r = lin >> 5;
            int c4 = (lin & 31) * 4;
            *(float4*)(sQ + r*QS + c4) = *(const float4*)(Qg + r*HD + c4);
        }
    }

    float m_i[4], l_i[4], acc[4][8];
#pragma unroll
    for (int i = 0; i < 4; i++) {
        m_i[i] = -INFINITY; l_i[i] = 0.f;
#pragma unroll
        for (int c = 0; c < 8; c++) acc[i][c] = 0.f;
    }

    const float scale = 0.08838834764831845f;

    for (int jc = 0; jc <= qt; jc++) {
        const float* Kg = g_k + ((size_t)bh*TT + jc*64)*HD;
        const float* Vg = g_v + ((size_t)bh*TT + jc*64)*HD;
#pragma unroll
        for (int i = 0; i < 8; i++) {
            int lin = tid + i*256;
            int r = lin >> 5;
            int c4 = (lin & 31) * 4;
            *(float4*)(sK + r*QS + c4) = *(const float4*)(Kg + r*HD + c4);
            *(float4*)(sV + r*QS + c4) = *(const float4*)(Vg + r*HD + c4);
        }
        __syncthreads();

        float s[4][4];
#pragma unroll
        for (int i = 0; i < 4; i++)
#pragma unroll
            for (int j = 0; j < 4; j++) s[i][j] = 0.f;

        for (int d = 0; d < 128; d += 4) {
            float4 a[4], b[4];
#pragma unroll
            for (int ii = 0; ii < 4; ii++)
                a[ii] = *(float4*)(sQ + (ty*4 + ii)*QS + d);
#pragma unroll
            for (int jj = 0; jj < 4; jj++)
                b[jj] = *(float4*)(sK + (tx*4 + jj)*QS + d);
#pragma unroll
            for (int ii = 0; ii < 4; ii++)
#pragma unroll
                for (int jj = 0; jj < 4; jj++) {
                    s[ii][jj] = fmaf(a[ii].x, b[jj].x, s[ii][jj]);
                    s[ii][jj] = fmaf(a[ii].y, b[jj].y, s[ii][jj]);
                    s[ii][jj] = fmaf(a[ii].z, b[jj].z, s[ii][jj]);
                    s[ii][jj] = fmaf(a[ii].w, b[jj].w, s[ii][jj]);
                }
        }

#pragma unroll
        for (int ii = 0; ii < 4; ii++) {
            int qrow = qt*64 + ty*4 + ii;
            float rowmax = -INFINITY;
#pragma unroll
            for (int jj = 0; jj < 4; jj++) {
                float sv = s[ii][jj] * scale;
                if (jc == qt && (jc*64 + tx*4 + jj) > qrow) sv = -INFINITY;
                s[ii][jj] = sv;
                rowmax = fmaxf(rowmax, sv);
            }
#pragma unroll
            for (int off = 8; off; off >>= 1)
                rowmax = fmaxf(rowmax, __shfl_xor_sync(0xffffffffu, rowmax, off));

            float m_new = fmaxf(m_i[ii], rowmax);
            float fac = __expf(m_i[ii] - m_new);
            float rsum = 0.f;
#pragma unroll
            for (int jj = 0; jj < 4; jj++) {
                float p = __expf(s[ii][jj] - m_new);
                s[ii][jj] = p;
                rsum += p;
            }
#pragma unroll
            for (int off = 8; off; off >>= 1)
                rsum += __shfl_xor_sync(0xffffffffu, rsum, off);

            l_i[ii] = l_i[ii]*fac + rsum;
            m_i[ii] = m_new;
#pragma unroll
            for (int cc = 0; cc < 8; cc++) acc[ii][cc] *= fac;
#pragma unroll
            for (int jj = 0; jj < 4; jj++)
                sP[(ty*4 + ii)*PS + tx*4 + jj] = s[ii][jj];
        }
        __syncthreads();

        for (int j = 0; j < 64; j++) {
            float p0 = sP[(ty*4 + 0)*PS + j];
            float p1 = sP[(ty*4 + 1)*PS + j];
            float p2 = sP[(ty*4 + 2)*PS + j];
            float p3 = sP[(ty*4 + 3)*PS + j];
            float4 v0 = *(float4*)(sV + j*QS + tx*8);
            float4 v1 = *(float4*)(sV + j*QS + tx*8 + 4);
            float vv[8] = {v0.x,v0.y,v0.z,v0.w,v1.x,v1.y,v1.z,v1.w};
#pragma unroll
            for (int cc = 0; cc < 8; cc++) {
                acc[0][cc] = fmaf(p0, vv[cc], acc[0][cc]);
                acc[1][cc] = fmaf(p1, vv[cc], acc[1][cc]);
                acc[2][cc] = fmaf(p2, vv[cc], acc[2][cc]);
                acc[3][cc] = fmaf(p3, vv[cc], acc[3][cc]);
            }
        }
        __syncthreads();
    }

    int b = bh >> 4;
    int h = bh & 15;
#pragma unroll
    for (int ii = 0; ii < 4; ii++) {
        int t = qt*64 + ty*4 + ii;
        float inv = 1.f / l_i[ii];
        float* yrow = g_y + ((size_t)(b*TT + t))*CC + h*HD + tx*8;
#pragma unroll
        for (int cc = 0; cc < 8; cc++)
            yrow[cc] = acc[ii][cc] * inv;
    }
}

// ---------------------------------------------------------------------------
// launch
// ---------------------------------------------------------------------------
extern "C" void kernel_launch(void* const* d_in, const int* in_sizes, int n_in,
                              void* d_out, int out_size)
{
    const float* x    = (const float*)d_in[0];
    const float* cosp = (const float*)d_in[1];
    const float* sinp = (const float*)d_in[2];
    const float* Wa   = (const float*)d_in[3];
    const float* Wp   = (const float*)d_in[4];
    float* out = (float*)d_out;

    // 1) qkv = x @ W_attn (tf32 tensor cores), scattered into head-major q/k/v
    gemm_tf32<0><<<dim3(N_QKV/128, MM/128), 256>>>(x, Wa, nullptr, MM, N_QKV, CC);

    // 2) RoPE on q,k
    rope_kernel<<<BB*NH*TT, 128>>>(cosp, sinp);

    // 3) flash attention -> g_y
    cudaFuncSetAttribute(flash_kernel, cudaFuncAttributeMaxDynamicSharedMemorySize,
                         (int)FLASH_SMEM);
    flash_kernel<<<dim3(TT/64, BB*NH), 256, FLASH_SMEM>>>();

    // 4) out = y @ W_proj (tf32 tensor cores)
    gemm_tf32<1><<<dim3(CC/128, MM/128), 256>>>(nullptr, Wp, out, MM, CC, CC);
}

// round 3
// speedup vs baseline: 5.7982x; 2.0509x over previous
#include <cuda_runtime.h>
#include <cuda_bf16.h>
#include <math.h>

// Problem constants
#define BB   2
#define TT   2048
#define CC   2048
#define NH   16
#define HD   128
#define MM   (BB*TT)        // 4096
#define N_QKV (3*CC)        // 6144

// ---------------------------------------------------------------------------
// Scratch (device globals; no runtime allocation)
// ---------------------------------------------------------------------------
__device__ float g_q[(size_t)BB*NH*TT*HD];   // [B,H,T,hd]
__device__ float g_k[(size_t)BB*NH*TT*HD];
__device__ float g_v[(size_t)BB*NH*TT*HD];
__device__ float g_y[(size_t)BB*TT*CC];      // attention output [B,T,C]

// ---------------------------------------------------------------------------
// TF32 helpers
// ---------------------------------------------------------------------------
__device__ __forceinline__ unsigned f2tf(float x) {
    unsigned r;
    asm("cvt.rna.tf32.f32 %0, %1;" : "=r"(r) : "f"(x));
    return r;
}

__device__ __forceinline__ void mma_tf32(float* c, const unsigned* a, const unsigned* b) {
    asm volatile(
        "mma.sync.aligned.m16n8k8.row.col.f32.tf32.tf32.f32 "
        "{%0,%1,%2,%3}, {%4,%5,%6,%7}, {%8,%9}, {%0,%1,%2,%3};"
        : "+f"(c[0]), "+f"(c[1]), "+f"(c[2]), "+f"(c[3])
        : "r"(a[0]), "r"(a[1]), "r"(a[2]), "r"(a[3]),
          "r"(b[0]), "r"(b[1]));
}

// ---------------------------------------------------------------------------
// TF32 tensor-core GEMM: C = A[M,K] @ B[K,N]   (unchanged from R2)
// ---------------------------------------------------------------------------
#define ASTR 20
#define BSTR 136

template <int MODE>
__global__ void __launch_bounds__(256)
gemm_tf32(const float* __restrict__ Ap, const float* __restrict__ Bp,
          float* __restrict__ Cp, int M, int N, int K)
{
    __shared__ unsigned As[2][128][ASTR];
    __shared__ unsigned Bs[2][16][BSTR];

    const float* A = (MODE == 0) ? Ap : (const float*)g_y;

    const int bx = blockIdx.x;
    const int by = blockIdx.y;
    const int tid  = threadIdx.x;
    const int lane = tid & 31;
    const int warp = tid >> 5;
    const int wm = warp >> 1;
    const int wn = warp & 1;
    const int tig = lane & 3;
    const int grp = lane >> 2;

    const int a_row = tid >> 2;
    const int a_kc  = (tid & 3) * 4;
    const int b_k   = tid >> 5;
    const int b_n4  = (tid & 31) * 4;

    const float* Abase = A  + (size_t)(by * 128) * K;
    const float* Bbase = Bp + bx * 128;

    float acc[2][8][4];
#pragma unroll
    for (int i = 0; i < 2; i++)
#pragma unroll
        for (int j = 0; j < 8; j++)
#pragma unroll
            for (int r = 0; r < 4; r++) acc[i][j][r] = 0.f;

    float4 pa0, pa1, pb0, pb1;

    pa0 = *(const float4*)(Abase + (size_t)a_row * K + a_kc);
    pa1 = *(const float4*)(Abase + (size_t)(a_row + 64) * K + a_kc);
    pb0 = *(const float4*)(Bbase + (size_t)b_k * N + b_n4);
    pb1 = *(const float4*)(Bbase + (size_t)(b_k + 8) * N + b_n4);
    {
        uint4 u;
        u.x = f2tf(pa0.x); u.y = f2tf(pa0.y); u.z = f2tf(pa0.z); u.w = f2tf(pa0.w);
        *(uint4*)&As[0][a_row][a_kc] = u;
        u.x = f2tf(pa1.x); u.y = f2tf(pa1.y); u.z = f2tf(pa1.z); u.w = f2tf(pa1.w);
        *(uint4*)&As[0][a_row + 64][a_kc] = u;
        u.x = f2tf(pb0.x); u.y = f2tf(pb0.y); u.z = f2tf(pb0.z); u.w = f2tf(pb0.w);
        *(uint4*)&Bs[0][b_k][b_n4] = u;
        u.x = f2tf(pb1.x); u.y = f2tf(pb1.y); u.z = f2tf(pb1.z); u.w = f2tf(pb1.w);
        *(uint4*)&Bs[0][b_k + 8][b_n4] = u;
    }
    __syncthreads();

    const int nk = K >> 4;
    for (int ks = 0; ks < nk; ks++) {
        const int s = ks & 1;

        if (ks + 1 < nk) {
            const int k0 = (ks + 1) << 4;
            pa0 = *(const float4*)(Abase + (size_t)a_row * K + k0 + a_kc);
            pa1 = *(const float4*)(Abase + (size_t)(a_row + 64) * K + k0 + a_kc);
            pb0 = *(const float4*)(Bbase + (size_t)(k0 + b_k) * N + b_n4);
            pb1 = *(const float4*)(Bbase + (size_t)(k0 + b_k + 8) * N + b_n4);
        }

#pragma unroll
        for (int kk = 0; kk < 2; kk++) {
            const int kb = kk * 8;
            unsigned af[2][4], bf[8][2];
#pragma unroll
            for (int mt = 0; mt < 2; mt++) {
                const int mr = wm * 32 + mt * 16 + grp;
                af[mt][0] = As[s][mr][kb + tig];
                af[mt][1] = As[s][mr + 8][kb + tig];
                af[mt][2] = As[s][mr][kb + tig + 4];
                af[mt][3] = As[s][mr + 8][kb + tig + 4];
            }
#pragma unroll
            for (int nt = 0; nt < 8; nt++) {
                const int nc = wn * 64 + nt * 8 + grp;
                bf[nt][0] = Bs[s][kb + tig][nc];
                bf[nt][1] = Bs[s][kb + tig + 4][nc];
            }
#pragma unroll
            for (int mt = 0; mt < 2; mt++)
#pragma unroll
                for (int nt = 0; nt < 8; nt++)
                    mma_tf32(acc[mt][nt], af[mt], bf[nt]);
        }

        if (ks + 1 < nk) {
            const int so = (ks + 1) & 1;
            uint4 u;
            u.x = f2tf(pa0.x); u.y = f2tf(pa0.y); u.z = f2tf(pa0.z); u.w = f2tf(pa0.w);
            *(uint4*)&As[so][a_row][a_kc] = u;
            u.x = f2tf(pa1.x); u.y = f2tf(pa1.y); u.z = f2tf(pa1.z); u.w = f2tf(pa1.w);
            *(uint4*)&As[so][a_row + 64][a_kc] = u;
            u.x = f2tf(pb0.x); u.y = f2tf(pb0.y); u.z = f2tf(pb0.z); u.w = f2tf(pb0.w);
            *(uint4*)&Bs[so][b_k][b_n4] = u;
            u.x = f2tf(pb1.x); u.y = f2tf(pb1.y); u.z = f2tf(pb1.z); u.w = f2tf(pb1.w);
            *(uint4*)&Bs[so][b_k + 8][b_n4] = u;
        }
        __syncthreads();
    }

#pragma unroll
    for (int mt = 0; mt < 2; mt++) {
        const int row0 = by * 128 + wm * 32 + mt * 16 + grp;
#pragma unroll
        for (int nt = 0; nt < 8; nt++) {
            const int col = bx * 128 + wn * 64 + nt * 8 + tig * 2;
            if (MODE == 0) {
#pragma unroll
                for (int half = 0; half < 2; half++) {
                    const int row = row0 + half * 8;
                    const int bb = row >> 11;
                    const int t  = row & 2047;
                    const int which = col >> 11;
                    const int c = col & 2047;
                    const int h = c >> 7;
                    const int dd = c & 127;
                    float* base = (which == 0) ? g_q : (which == 1) ? g_k : g_v;
                    float* dst = base + ((size_t)(bb * NH + h) * TT + t) * HD + dd;
                    *(float2*)dst = make_float2(acc[mt][nt][half * 2],
                                                acc[mt][nt][half * 2 + 1]);
                }
            } else {
                *(float2*)(Cp + (size_t)row0 * N + col) =
                    make_float2(acc[mt][nt][0], acc[mt][nt][1]);
                *(float2*)(Cp + (size_t)(row0 + 8) * N + col) =
                    make_float2(acc[mt][nt][2], acc[mt][nt][3]);
            }
        }
    }
}

// ---------------------------------------------------------------------------
// RoPE kernel (unchanged)
// ---------------------------------------------------------------------------
__global__ void rope_kernel(const float* __restrict__ cosp,
                            const float* __restrict__ sinp)
{
    int row = blockIdx.x;
    int t = row & (TT - 1);
    int tid = threadIdx.x;
    int d = tid & 63;
    float* arr = (tid < 64) ? g_q : g_k;
    float* base = arr + (size_t)row * HD;
    float c = cosp[t*64 + d];
    float s = sinp[t*64 + d];
    float x1 = base[d];
    float x2 = base[d + 64];
    base[d]      = x1*c - x2*s;
    base[d + 64] = x1*s + x2*c;
}

// ---------------------------------------------------------------------------
// Flash attention v2: TF32 tensor-core MMA.
// Br=128 (8 warps x 16 rows), Bc=64, hd=128. Online softmax on fragments.
// P goes through warp-private smem to convert C-fragment -> A-fragment layout.
// ---------------------------------------------------------------------------
#define FBR 128
#define FBC 64
#define FKS 132     // Q/K/V smem row stride (words)
#define FPS 68      // P smem row stride (words)
#define FLASH2_SMEM ((FBR*FKS + 2*FBC*FKS + 8*16*FPS) * 4)   // 169,984 B

__global__ void __launch_bounds__(256)
flash2_kernel()
{
    extern __shared__ unsigned sm[];
    unsigned* uQ = sm;                        // [128][FKS]
    unsigned* uK = uQ + FBR*FKS;              // [64][FKS]
    unsigned* uV = uK + FBC*FKS;              // [64][FKS]
    unsigned* uP = uV + FBC*FKS;              // [8][16][FPS]

    const int qt  = blockIdx.x;
    const int bh  = blockIdx.y;
    const int tid = threadIdx.x;
    const int lane = tid & 31;
    const int wq   = tid >> 5;        // warp id: rows [wq*16, wq*16+16)
    const int tig  = lane & 3;
    const int grp  = lane >> 2;

    // load + convert Q tile
    {
        const float* Qg = g_q + ((size_t)bh*TT + qt*FBR)*HD;
#pragma unroll
        for (int i = 0; i < FBR*HD/4/256; i++) {
            int lin = tid + i*256;
            int r  = lin >> 5;
            int c4 = (lin & 31) * 4;
            float4 v = *(const float4*)(Qg + (size_t)r*HD + c4);
            uint4 u;
            u.x = f2tf(v.x); u.y = f2tf(v.y); u.z = f2tf(v.z); u.w = f2tf(v.w);
            *(uint4*)&uQ[r*FKS + c4] = u;
        }
    }

    float m_i[2], l_i[2];
    m_i[0] = m_i[1] = -1e30f;
    l_i[0] = l_i[1] = 0.f;
    float oc[16][4];
#pragma unroll
    for (int n = 0; n < 16; n++)
#pragma unroll
        for (int r = 0; r < 4; r++) oc[n][r] = 0.f;

    const float scale = 0.08838834764831845f;   // 1/sqrt(128)
    const int warp_row0 = qt*FBR + wq*16;       // warp's min global row
    const int nblocks = 2*qt + 2;

    for (int jc = 0; jc < nblocks; jc++) {
        __syncthreads();   // all warps done reading uK/uV of previous iter
        // load + convert K,V tiles
        {
            const float* Kg = g_k + ((size_t)bh*TT + jc*FBC)*HD;
            const float* Vg = g_v + ((size_t)bh*TT + jc*FBC)*HD;
#pragma unroll
            for (int i = 0; i < FBC*HD/4/256; i++) {
                int lin = tid + i*256;
                int r  = lin >> 5;
                int c4 = (lin & 31) * 4;
                float4 a = *(const float4*)(Kg + (size_t)r*HD + c4);
                uint4 u;
                u.x = f2tf(a.x); u.y = f2tf(a.y); u.z = f2tf(a.z); u.w = f2tf(a.w);
                *(uint4*)&uK[r*FKS + c4] = u;
                float4 b = *(const float4*)(Vg + (size_t)r*HD + c4);
                u.x = f2tf(b.x); u.y = f2tf(b.y); u.z = f2tf(b.z); u.w = f2tf(b.w);
                *(uint4*)&uV[r*FKS + c4] = u;
            }
        }
        __syncthreads();

        // per-warp early out: block entirely above the diagonal for this warp
        if (jc*FBC > warp_row0 + 15) continue;

        // ---- S = Q K^T  (16 x 64 per warp) ----
        float sc[8][4];
#pragma unroll
        for (int n = 0; n < 8; n++)
#pragma unroll
            for (int r = 0; r < 4; r++) sc[n][r] = 0.f;

#pragma unroll
        for (int ks = 0; ks < 16; ks++) {
            const int d0 = ks*8;
            unsigned af[4];
            af[0] = uQ[(wq*16 + grp    )*FKS + d0 + tig];
            af[1] = uQ[(wq*16 + grp + 8)*FKS + d0 + tig];
            af[2] = uQ[(wq*16 + grp    )*FKS + d0 + tig + 4];
            af[3] = uQ[(wq*16 + grp + 8)*FKS + d0 + tig + 4];
#pragma unroll
            for (int nt = 0; nt < 8; nt++) {
                unsigned bf[2];
                bf[0] = uK[(nt*8 + grp)*FKS + d0 + tig];
                bf[1] = uK[(nt*8 + grp)*FKS + d0 + tig + 4];
                mma_tf32(sc[nt], af, bf);
            }
        }

        // ---- online softmax on fragments ----
        unsigned* Pw = uP + wq*16*FPS;
#pragma unroll
        for (int h = 0; h < 2; h++) {
            const int row = warp_row0 + grp + h*8;
            float rmax = -1e30f;
#pragma unroll
            for (int nt = 0; nt < 8; nt++) {
#pragma unroll
                for (int c = 0; c < 2; c++) {
                    const int col = jc*FBC + nt*8 + tig*2 + c;
                    float v = sc[nt][h*2 + c] * scale;
                    if (col > row) v = -1e30f;
                    sc[nt][h*2 + c] = v;
                    rmax = fmaxf(rmax, v);
                }
            }
            rmax = fmaxf(rmax, __shfl_xor_sync(0xffffffffu, rmax, 1));
            rmax = fmaxf(rmax, __shfl_xor_sync(0xffffffffu, rmax, 2));

            const float m_new = fmaxf(m_i[h], rmax);
            const float fac = __expf(m_i[h] - m_new);
            float rsum = 0.f;
#pragma unroll
            for (int nt = 0; nt < 8; nt++) {
#pragma unroll
                for (int c = 0; c < 2; c++) {
                    float p = __expf(sc[nt][h*2 + c] - m_new);
                    sc[nt][h*2 + c] = p;
                    rsum += p;
                    Pw[(grp + h*8)*FPS + nt*8 + tig*2 + c] = f2tf(p);
                }
            }
            rsum += __shfl_xor_sync(0xffffffffu, rsum, 1);
            rsum += __shfl_xor_sync(0xffffffffu, rsum, 2);

            l_i[h] = l_i[h]*fac + rsum;
            m_i[h] = m_new;
#pragma unroll
            for (int nt = 0; nt < 16; nt++) {
                oc[nt][h*2]     *= fac;
                oc[nt][h*2 + 1] *= fac;
            }
        }
        __syncwarp();

        // ---- O += P V  (16 x 128 per warp) ----
#pragma unroll
        for (int k0 = 0; k0 < FBC; k0 += 8) {
            unsigned af[4];
            af[0] = Pw[(grp    )*FPS + k0 + tig];
            af[1] = Pw[(grp + 8)*FPS + k0 + tig];
            af[2] = Pw[(grp    )*FPS + k0 + tig + 4];
            af[3] = Pw[(grp + 8)*FPS + k0 + tig + 4];
#pragma unroll
            for (int nt = 0; nt < 16; nt++) {
                unsigned bf[2];
                bf[0] = uV[(k0 + tig    )*FKS + nt*8 + grp];
                bf[1] = uV[(k0 + tig + 4)*FKS + nt*8 + grp];
                mma_tf32(oc[nt], af, bf);
            }
        }
    }

    // epilogue: y[b, t, h*128 + d]
    const int b = bh >> 4;
    const int h = bh & 15;
#pragma unroll
    for (int hh = 0; hh < 2; hh++) {
        const int t = qt*FBR + wq*16 + grp + hh*8;
        const float inv = 1.f / l_i[hh];
        float* yrow = g_y + ((size_t)(b*TT + t))*CC + h*HD;
#pragma unroll
        for (int nt = 0; nt < 16; nt++) {
            *(float2*)(yrow + nt*8 + tig*2) =
                make_float2(oc[nt][hh*2] * inv, oc[nt][hh*2 + 1] * inv);
        }
    }
}

// ---------------------------------------------------------------------------
// launch
// ---------------------------------------------------------------------------
extern "C" void kernel_launch(void* const* d_in, const int* in_sizes, int n_in,
                              void* d_out, int out_size)
{
    const float* x    = (const float*)d_in[0];
    const float* cosp = (const float*)d_in[1];
    const float* sinp = (const float*)d_in[2];
    const float* Wa   = (const float*)d_in[3];
    const float* Wp   = (const float*)d_in[4];
    float* out = (float*)d_out;

    // 1) qkv = x @ W_attn (tf32 tensor cores), scattered into head-major q/k/v
    gemm_tf32<0><<<dim3(N_QKV/128, MM/128), 256>>>(x, Wa, nullptr, MM, N_QKV, CC);

    // 2) RoPE on q,k
    rope_kernel<<<BB*NH*TT, 128>>>(cosp, sinp);

    // 3) flash attention (tf32 tensor cores) -> g_y
    cudaFuncSetAttribute(flash2_kernel, cudaFuncAttributeMaxDynamicSharedMemorySize,
                         (int)FLASH2_SMEM);
    flash2_kernel<<<dim3(TT/FBR, BB*NH), 256, FLASH2_SMEM>>>();

    // 4) out = y @ W_proj (tf32 tensor cores)
    gemm_tf32<1><<<dim3(CC/128, MM/128), 256>>>(nullptr, Wp, out, MM, CC, CC);
}

// round 4
// speedup vs baseline: 5.8335x; 1.0061x over previous
#include <cuda_runtime.h>
#include <cuda_bf16.h>
#include <math.h>

// Problem constants
#define BB   2
#define TT   2048
#define CC   2048
#define NH   16
#define HD   128
#define MM   (BB*TT)        // 4096
#define N_QKV (3*CC)        // 6144

// ---------------------------------------------------------------------------
// Scratch (device globals; no runtime allocation)
// ---------------------------------------------------------------------------
__device__ float g_q[(size_t)BB*NH*TT*HD];   // [B,H,T,hd]
__device__ float g_k[(size_t)BB*NH*TT*HD];
__device__ float g_v[(size_t)BB*NH*TT*HD];   // pre-rounded tf32 bits
__device__ float g_y[(size_t)BB*TT*CC];      // pre-rounded tf32 bits
__device__ float g_x[(size_t)MM*CC];         // pre-rounded x
__device__ float g_wa[(size_t)CC*N_QKV];     // pre-rounded W_attn
__device__ float g_wp[(size_t)CC*CC];        // pre-rounded W_proj

// ---------------------------------------------------------------------------
// TF32 helpers
// ---------------------------------------------------------------------------
__device__ __forceinline__ unsigned f2tf(float x) {
    unsigned r;
    asm("cvt.rna.tf32.f32 %0, %1;" : "=r"(r) : "f"(x));
    return r;
}
__device__ __forceinline__ float f2tf_f(float x) {
    return __uint_as_float(f2tf(x));
}

__device__ __forceinline__ void mma_tf32(float* c, const unsigned* a, const unsigned* b) {
    asm volatile(
        "mma.sync.aligned.m16n8k8.row.col.f32.tf32.tf32.f32 "
        "{%0,%1,%2,%3}, {%4,%5,%6,%7}, {%8,%9}, {%0,%1,%2,%3};"
        : "+f"(c[0]), "+f"(c[1]), "+f"(c[2]), "+f"(c[3])
        : "r"(a[0]), "r"(a[1]), "r"(a[2]), "r"(a[3]),
          "r"(b[0]), "r"(b[1]));
}

// cp.async helpers
__device__ __forceinline__ void cpasync16(void* smem_dst, const void* gsrc) {
    unsigned s = (unsigned)__cvta_generic_to_shared(smem_dst);
    asm volatile("cp.async.cg.shared.global [%0], [%1], 16;\n" :: "r"(s), "l"(gsrc));
}
__device__ __forceinline__ void cpasync_commit() {
    asm volatile("cp.async.commit_group;\n");
}
template <int N>
__device__ __forceinline__ void cpasync_wait() {
    asm volatile("cp.async.wait_group %0;\n" :: "n"(N));
}

// ---------------------------------------------------------------------------
// Pre-round fp32 -> tf32 bits (elementwise, float4 grid-stride)
// ---------------------------------------------------------------------------
__global__ void cvt_tf32_kernel(const float4* __restrict__ in,
                                float4* __restrict__ out, int n4)
{
    for (int i = blockIdx.x * blockDim.x + threadIdx.x; i < n4;
         i += gridDim.x * blockDim.x) {
        float4 v = in[i];
        v.x = f2tf_f(v.x); v.y = f2tf_f(v.y); v.z = f2tf_f(v.z); v.w = f2tf_f(v.w);
        out[i] = v;
    }
}

// ---------------------------------------------------------------------------
// TF32 tensor-core GEMM with cp.async 3-stage pipeline.
// Inputs already tf32-rounded in gmem; no conversions in kernel.
// 128x128 tile, BK=16, 256 threads, 8 warps (4M x 2N), warp tile 32x64.
// MODE 0: A=g_x, B=g_wa, epilogue scatters into g_q/g_k/g_v (v pre-rounded)
// MODE 1: A=g_y, B=g_wp, epilogue writes row-major C (d_out)
// ---------------------------------------------------------------------------
#define ASTR 20    // 80B row stride = 5*16B (keeps 16B alignment for cp.async)
#define BSTR 136   // 544B row stride = 34*16B
#define STAGES 3

template <int MODE>
__global__ void __launch_bounds__(256)
gemm_tf32(float* __restrict__ Cp, int M, int N, int K)
{
    __shared__ unsigned As[STAGES][128][ASTR];
    __shared__ unsigned Bs[STAGES][16][BSTR];

    const float* A = (MODE == 0) ? g_x : g_y;
    const float* B = (MODE == 0) ? g_wa : g_wp;

    const int bx = blockIdx.x;
    const int by = blockIdx.y;
    const int tid  = threadIdx.x;
    const int lane = tid & 31;
    const int warp = tid >> 5;
    const int wm = warp >> 1;
    const int wn = warp & 1;
    const int tig = lane & 3;
    const int grp = lane >> 2;

    const int a_row = tid >> 2;          // 0..63 (and +64)
    const int a_kc  = (tid & 3) * 4;
    const int b_k   = tid >> 5;          // 0..7 (and +8)
    const int b_n4  = (tid & 31) * 4;

    const float* Abase = A + (size_t)(by * 128) * K;
    const float* Bbase = B + bx * 128;

    float acc[2][8][4];
#pragma unroll
    for (int i = 0; i < 2; i++)
#pragma unroll
        for (int j = 0; j < 8; j++)
#pragma unroll
            for (int r = 0; r < 4; r++) acc[i][j][r] = 0.f;

    const int nk = K >> 4;

    // pipeline prologue: issue stages 0 and 1
#pragma unroll
    for (int p = 0; p < STAGES - 1; p++) {
        const int k0 = p << 4;
        cpasync16(&As[p][a_row][a_kc],      Abase + (size_t)a_row * K + k0 + a_kc);
        cpasync16(&As[p][a_row + 64][a_kc], Abase + (size_t)(a_row + 64) * K + k0 + a_kc);
        cpasync16(&Bs[p][b_k][b_n4],        Bbase + (size_t)(k0 + b_k) * N + b_n4);
        cpasync16(&Bs[p][b_k + 8][b_n4],    Bbase + (size_t)(k0 + b_k + 8) * N + b_n4);
        cpasync_commit();
    }

    for (int ks = 0; ks < nk; ks++) {
        const int s = ks % STAGES;
        cpasync_wait<STAGES - 2>();
        __syncthreads();

        // compute on stage s: 2 k-chunks of 8
#pragma unroll
        for (int kk = 0; kk < 2; kk++) {
            const int kb = kk * 8;
            unsigned af[2][4], bf[8][2];
#pragma unroll
            for (int mt = 0; mt < 2; mt++) {
                const int mr = wm * 32 + mt * 16 + grp;
                af[mt][0] = As[s][mr][kb + tig];
                af[mt][1] = As[s][mr + 8][kb + tig];
                af[mt][2] = As[s][mr][kb + tig + 4];
                af[mt][3] = As[s][mr + 8][kb + tig + 4];
            }
#pragma unroll
            for (int nt = 0; nt < 8; nt++) {
                const int nc = wn * 64 + nt * 8 + grp;
                bf[nt][0] = Bs[s][kb + tig][nc];
                bf[nt][1] = Bs[s][kb + tig + 4][nc];
            }
#pragma unroll
            for (int mt = 0; mt < 2; mt++)
#pragma unroll
                for (int nt = 0; nt < 8; nt++)
                    mma_tf32(acc[mt][nt], af[mt], bf[nt]);
        }

        // issue loads for stage ks+2
        if (ks + STAGES - 1 < nk) {
            const int so = (ks + STAGES - 1) % STAGES;
            const int k0 = (ks + STAGES - 1) << 4;
            cpasync16(&As[so][a_row][a_kc],      Abase + (size_t)a_row * K + k0 + a_kc);
            cpasync16(&As[so][a_row + 64][a_kc], Abase + (size_t)(a_row + 64) * K + k0 + a_kc);
            cpasync16(&Bs[so][b_k][b_n4],        Bbase + (size_t)(k0 + b_k) * N + b_n4);
            cpasync16(&Bs[so][b_k + 8][b_n4],    Bbase + (size_t)(k0 + b_k + 8) * N + b_n4);
        }
        cpasync_commit();
    }

    // epilogue
#pragma unroll
    for (int mt = 0; mt < 2; mt++) {
        const int row0 = by * 128 + wm * 32 + mt * 16 + grp;
#pragma unroll
        for (int nt = 0; nt < 8; nt++) {
            const int col = bx * 128 + wn * 64 + nt * 8 + tig * 2;
            if (MODE == 0) {
#pragma unroll
                for (int half = 0; half < 2; half++) {
                    const int row = row0 + half * 8;
                    const int bb = row >> 11;
                    const int t  = row & 2047;
                    const int which = col >> 11;
                    const int c = col & 2047;
                    const int h = c >> 7;
                    const int dd = c & 127;
                    float* base = (which == 0) ? g_q : (which == 1) ? g_k : g_v;
                    float* dst = base + ((size_t)(bb * NH + h) * TT + t) * HD + dd;
                    float v0 = acc[mt][nt][half * 2];
                    float v1 = acc[mt][nt][half * 2 + 1];
                    if (which == 2) { v0 = f2tf_f(v0); v1 = f2tf_f(v1); }  // V pre-rounded
                    *(float2*)dst = make_float2(v0, v1);
                }
            } else {
                *(float2*)(Cp + (size_t)row0 * N + col) =
                    make_float2(acc[mt][nt][0], acc[mt][nt][1]);
                *(float2*)(Cp + (size_t)(row0 + 8) * N + col) =
                    make_float2(acc[mt][nt][2], acc[mt][nt][3]);
            }
        }
    }
}

// ---------------------------------------------------------------------------
// RoPE kernel: rotate q,k in place and pre-round to tf32 bits.
// ---------------------------------------------------------------------------
__global__ void rope_kernel(const float* __restrict__ cosp,
                            const float* __restrict__ sinp)
{
    int row = blockIdx.x;
    int t = row & (TT - 1);
    int tid = threadIdx.x;
    int d = tid & 63;
    float* arr = (tid < 64) ? g_q : g_k;
    float* base = arr + (size_t)row * HD;
    float c = cosp[t*64 + d];
    float s = sinp[t*64 + d];
    float x1 = base[d];
    float x2 = base[d + 64];
    base[d]      = f2tf_f(x1*c - x2*s);
    base[d + 64] = f2tf_f(x1*s + x2*c);
}

// ---------------------------------------------------------------------------
// Flash attention: TF32 MMA, Br=128 (8 warps x 16 rows), Bc=64.
// Inputs pre-rounded; no conversions on the load path.
// ---------------------------------------------------------------------------
#define FBR 128
#define FBC 64
#define FKS 132
#define FPS 68
#define FLASH2_SMEM ((FBR*FKS + 2*FBC*FKS + 8*16*FPS) * 4)

__global__ void __launch_bounds__(256)
flash2_kernel()
{
    extern __shared__ unsigned sm[];
    unsigned* uQ = sm;
    unsigned* uK = uQ + FBR*FKS;
    unsigned* uV = uK + FBC*FKS;
    unsigned* uP = uV + FBC*FKS;

    const int qt  = blockIdx.x;
    const int bh  = blockIdx.y;
    const int tid = threadIdx.x;
    const int lane = tid & 31;
    const int wq   = tid >> 5;
    const int tig  = lane & 3;
    const int grp  = lane >> 2;

    // load Q tile (already tf32 bits)
    {
        const float* Qg = g_q + ((size_t)bh*TT + qt*FBR)*HD;
#pragma unroll
        for (int i = 0; i < FBR*HD/4/256; i++) {
            int lin = tid + i*256;
            int r  = lin >> 5;
            int c4 = (lin & 31) * 4;
            *(float4*)&uQ[r*FKS + c4] = *(const float4*)(Qg + (size_t)r*HD + c4);
        }
    }

    float m_i[2], l_i[2];
    m_i[0] = m_i[1] = -1e30f;
    l_i[0] = l_i[1] = 0.f;
    float oc[16][4];
#pragma unroll
    for (int n = 0; n < 16; n++)
#pragma unroll
        for (int r = 0; r < 4; r++) oc[n][r] = 0.f;

    const float scale = 0.08838834764831845f;
    const int warp_row0 = qt*FBR + wq*16;
    const int nblocks = 2*qt + 2;

    for (int jc = 0; jc < nblocks; jc++) {
        __syncthreads();
        {
            const float* Kg = g_k + ((size_t)bh*TT + jc*FBC)*HD;
            const float* Vg = g_v + ((size_t)bh*TT + jc*FBC)*HD;
#pragma unroll
            for (int i = 0; i < FBC*HD/4/256; i++) {
                int lin = tid + i*256;
                int r  = lin >> 5;
                int c4 = (lin & 31) * 4;
                *(float4*)&uK[r*FKS + c4] = *(const float4*)(Kg + (size_t)r*HD + c4);
                *(float4*)&uV[r*FKS + c4] = *(const float4*)(Vg + (size_t)r*HD + c4);
            }
        }
        __syncthreads();

        if (jc*FBC > warp_row0 + 15) continue;

        // ---- S = Q K^T ----
        float sc[8][4];
#pragma unroll
        for (int n = 0; n < 8; n++)
#pragma unroll
            for (int r = 0; r < 4; r++) sc[n][r] = 0.f;

#pragma unroll
        for (int ks = 0; ks < 16; ks++) {
            const int d0 = ks*8;
            unsigned af[4];
            af[0] = uQ[(wq*16 + grp    )*FKS + d0 + tig];
            af[1] = uQ[(wq*16 + grp + 8)*FKS + d0 + tig];
            af[2] = uQ[(wq*16 + grp    )*FKS + d0 + tig + 4];
            af[3] = uQ[(wq*16 + grp + 8)*FKS + d0 + tig + 4];
#pragma unroll
            for (int nt = 0; nt < 8; nt++) {
                unsigned bf[2];
                bf[0] = uK[(nt*8 + grp)*FKS + d0 + tig];
                bf[1] = uK[(nt*8 + grp)*FKS + d0 + tig + 4];
                mma_tf32(sc[nt], af, bf);
            }
        }

        // ---- online softmax ----
        unsigned* Pw = uP + wq*16*FPS;
#pragma unroll
        for (int h = 0; h < 2; h++) {
            const int row = warp_row0 + grp + h*8;
            float rmax = -1e30f;
#pragma unroll
            for (int nt = 0; nt < 8; nt++) {
#pragma unroll
                for (int c = 0; c < 2; c++) {
                    const int col = jc*FBC + nt*8 + tig*2 + c;
                    float v = sc[nt][h*2 + c] * scale;
                    if (col > row) v = -1e30f;
                    sc[nt][h*2 + c] = v;
                    rmax = fmaxf(rmax, v);
                }
            }
            rmax = fmaxf(rmax, __shfl_xor_sync(0xffffffffu, rmax, 1));
            rmax = fmaxf(rmax, __shfl_xor_sync(0xffffffffu, rmax, 2));

            const float m_new = fmaxf(m_i[h], rmax);
            const float fac = __expf(m_i[h] - m_new);
            float rsum = 0.f;
#pragma unroll
            for (int nt = 0; nt < 8; nt++) {
#pragma unroll
                for (int c = 0; c < 2; c++) {
                    float p = __expf(sc[nt][h*2 + c] - m_new);
                    sc[nt][h*2 + c] = p;
                    rsum += p;
                    Pw[(grp + h*8)*FPS + nt*8 + tig*2 + c] = f2tf(p);
                }
            }
            rsum += __shfl_xor_sync(0xffffffffu, rsum, 1);
            rsum += __shfl_xor_sync(0xffffffffu, rsum, 2);

            l_i[h] = l_i[h]*fac + rsum;
            m_i[h] = m_new;
#pragma unroll
            for (int nt = 0; nt < 16; nt++) {
                oc[nt][h*2]     *= fac;
                oc[nt][h*2 + 1] *= fac;
            }
        }
        __syncwarp();

        // ---- O += P V ----
#pragma unroll
        for (int k0 = 0; k0 < FBC; k0 += 8) {
            unsigned af[4];
            af[0] = Pw[(grp    )*FPS + k0 + tig];
            af[1] = Pw[(grp + 8)*FPS + k0 + tig];
            af[2] = Pw[(grp    )*FPS + k0 + tig + 4];
            af[3] = Pw[(grp + 8)*FPS + k0 + tig + 4];
#pragma unroll
            for (int nt = 0; nt < 16; nt++) {
                unsigned bf[2];
                bf[0] = uV[(k0 + tig    )*FKS + nt*8 + grp];
                bf[1] = uV[(k0 + tig + 4)*FKS + nt*8 + grp];
                mma_tf32(oc[nt], af, bf);
            }
        }
    }

    // epilogue: y pre-rounded for gemm<1>
    const int b = bh >> 4;
    const int h = bh & 15;
#pragma unroll
    for (int hh = 0; hh < 2; hh++) {
        const int t = qt*FBR + wq*16 + grp + hh*8;
        const float inv = 1.f / l_i[hh];
        float* yrow = g_y + ((size_t)(b*TT + t))*CC + h*HD;
#pragma unroll
        for (int nt = 0; nt < 16; nt++) {
            *(float2*)(yrow + nt*8 + tig*2) =
                make_float2(f2tf_f(oc[nt][hh*2] * inv),
                            f2tf_f(oc[nt][hh*2 + 1] * inv));
        }
    }
}

// ---------------------------------------------------------------------------
// launch
// ---------------------------------------------------------------------------
extern "C" void kernel_launch(void* const* d_in, const int* in_sizes, int n_in,
                              void* d_out, int out_size)
{
    const float* x    = (const float*)d_in[0];
    const float* cosp = (const float*)d_in[1];
    const float* sinp = (const float*)d_in[2];
    const float* Wa   = (const float*)d_in[3];
    const float* Wp   = (const float*)d_in[4];
    float* out = (float*)d_out;

    float *dx, *dwa, *dwp;
    cudaGetSymbolAddress((void**)&dx,  g_x);
    cudaGetSymbolAddress((void**)&dwa, g_wa);
    cudaGetSymbolAddress((void**)&dwp, g_wp);

    // 0) pre-round operands to tf32 bits
    cvt_tf32_kernel<<<2048, 256>>>((const float4*)x,  (float4*)dx,  MM*CC/4);
    cvt_tf32_kernel<<<2048, 256>>>((const float4*)Wa, (float4*)dwa, CC*N_QKV/4);
    cvt_tf32_kernel<<<2048, 256>>>((const float4*)Wp, (float4*)dwp, CC*CC/4);

    // 1) qkv = x @ W_attn -> head-major q/k/v
    gemm_tf32<0><<<dim3(N_QKV/128, MM/128), 256>>>(nullptr, MM, N_QKV, CC);

    // 2) RoPE on q,k (writes tf32-rounded)
    rope_kernel<<<BB*NH*TT, 128>>>(cosp, sinp);

    // 3) flash attention -> g_y (tf32-rounded)
    cudaFuncSetAttribute(flash2_kernel, cudaFuncAttributeMaxDynamicSharedMemorySize,
                         (int)FLASH2_SMEM);
    flash2_kernel<<<dim3(TT/FBR, BB*NH), 256, FLASH2_SMEM>>>();

    // 4) out = y @ W_proj
    gemm_tf32<1><<<dim3(CC/128, MM/128), 256>>>(out, MM, CC, CC);
}

// round 5
// speedup vs baseline: 6.5669x; 1.1257x over previous
#include <cuda_runtime.h>
#include <cuda_bf16.h>
#include <math.h>

// Problem constants
#define BB   2
#define TT   2048
#define CC   2048
#define NH   16
#define HD   128
#define MM   (BB*TT)        // 4096
#define N_QKV (3*CC)        // 6144

// ---------------------------------------------------------------------------
// Scratch (device globals; no runtime allocation)
// ---------------------------------------------------------------------------
__device__ float g_q[(size_t)BB*NH*TT*HD];   // [B,H,T,hd]
__device__ float g_k[(size_t)BB*NH*TT*HD];
__device__ float g_v[(size_t)BB*NH*TT*HD];   // pre-rounded tf32 bits
__device__ float g_y[(size_t)BB*TT*CC];      // pre-rounded tf32 bits
__device__ float g_x[(size_t)MM*CC];         // pre-rounded x
__device__ float g_wa[(size_t)CC*N_QKV];     // pre-rounded W_attn
__device__ float g_wp[(size_t)CC*CC];        // pre-rounded W_proj

// ---------------------------------------------------------------------------
// TF32 helpers
// ---------------------------------------------------------------------------
__device__ __forceinline__ unsigned f2tf(float x) {
    unsigned r;
    asm("cvt.rna.tf32.f32 %0, %1;" : "=r"(r) : "f"(x));
    return r;
}
__device__ __forceinline__ float f2tf_f(float x) {
    return __uint_as_float(f2tf(x));
}

__device__ __forceinline__ void mma_tf32(float* c, const unsigned* a, const unsigned* b) {
    asm volatile(
        "mma.sync.aligned.m16n8k8.row.col.f32.tf32.tf32.f32 "
        "{%0,%1,%2,%3}, {%4,%5,%6,%7}, {%8,%9}, {%0,%1,%2,%3};"
        : "+f"(c[0]), "+f"(c[1]), "+f"(c[2]), "+f"(c[3])
        : "r"(a[0]), "r"(a[1]), "r"(a[2]), "r"(a[3]),
          "r"(b[0]), "r"(b[1]));
}

// cp.async helpers
__device__ __forceinline__ void cpasync16(void* smem_dst, const void* gsrc) {
    unsigned s = (unsigned)__cvta_generic_to_shared(smem_dst);
    asm volatile("cp.async.cg.shared.global [%0], [%1], 16;\n" :: "r"(s), "l"(gsrc));
}
__device__ __forceinline__ void cpasync_commit() {
    asm volatile("cp.async.commit_group;\n");
}
template <int N>
__device__ __forceinline__ void cpasync_wait() {
    asm volatile("cp.async.wait_group %0;\n" :: "n"(N));
}

// ---------------------------------------------------------------------------
// Pre-round fp32 -> tf32 bits (elementwise, float4 grid-stride)
// ---------------------------------------------------------------------------
__global__ void cvt_tf32_kernel(const float4* __restrict__ in,
                                float4* __restrict__ out, int n4)
{
    for (int i = blockIdx.x * blockDim.x + threadIdx.x; i < n4;
         i += gridDim.x * blockDim.x) {
        float4 v = in[i];
        v.x = f2tf_f(v.x); v.y = f2tf_f(v.y); v.z = f2tf_f(v.z); v.w = f2tf_f(v.w);
        out[i] = v;
    }
}

// ---------------------------------------------------------------------------
// TF32 tensor-core GEMM with cp.async 3-stage pipeline, 2 CTAs/SM.
// 128x128 tile, BK=16, 256 threads, 8 warps (4M x 2N), warp tile 32x64.
// MODE 0: A=g_x, B=g_wa, epilogue scatters into g_q/g_k/g_v (v pre-rounded)
// MODE 1: A=g_y, B=g_wp, epilogue writes row-major C (d_out)
// ---------------------------------------------------------------------------
#define ASTR 20
#define BSTR 136
#define STAGES 3

template <int MODE>
__global__ void __launch_bounds__(256, 2)
gemm_tf32(float* __restrict__ Cp, int M, int N, int K)
{
    __shared__ unsigned As[STAGES][128][ASTR];
    __shared__ unsigned Bs[STAGES][16][BSTR];

    const float* A = (MODE == 0) ? g_x : g_y;
    const float* B = (MODE == 0) ? g_wa : g_wp;

    const int bx = blockIdx.x;
    const int by = blockIdx.y;
    const int tid  = threadIdx.x;
    const int lane = tid & 31;
    const int warp = tid >> 5;
    const int wm = warp >> 1;
    const int wn = warp & 1;
    const int tig = lane & 3;
    const int grp = lane >> 2;

    const int a_row = tid >> 2;          // 0..63 (and +64)
    const int a_kc  = (tid & 3) * 4;
    const int b_k   = tid >> 5;          // 0..7 (and +8)
    const int b_n4  = (tid & 31) * 4;

    const float* Abase = A + (size_t)(by * 128) * K;
    const float* Bbase = B + bx * 128;

    float acc[2][8][4];
#pragma unroll
    for (int i = 0; i < 2; i++)
#pragma unroll
        for (int j = 0; j < 8; j++)
#pragma unroll
            for (int r = 0; r < 4; r++) acc[i][j][r] = 0.f;

    const int nk = K >> 4;

    // pipeline prologue: issue stages 0 and 1
#pragma unroll
    for (int p = 0; p < STAGES - 1; p++) {
        const int k0 = p << 4;
        cpasync16(&As[p][a_row][a_kc],      Abase + (size_t)a_row * K + k0 + a_kc);
        cpasync16(&As[p][a_row + 64][a_kc], Abase + (size_t)(a_row + 64) * K + k0 + a_kc);
        cpasync16(&Bs[p][b_k][b_n4],        Bbase + (size_t)(k0 + b_k) * N + b_n4);
        cpasync16(&Bs[p][b_k + 8][b_n4],    Bbase + (size_t)(k0 + b_k + 8) * N + b_n4);
        cpasync_commit();
    }

    for (int ks = 0; ks < nk; ks++) {
        const int s = ks % STAGES;
        cpasync_wait<STAGES - 2>();
        __syncthreads();

        // compute on stage s: 2 k-chunks of 8
#pragma unroll
        for (int kk = 0; kk < 2; kk++) {
            const int kb = kk * 8;
            unsigned af[2][4], bf[8][2];
#pragma unroll
            for (int mt = 0; mt < 2; mt++) {
                const int mr = wm * 32 + mt * 16 + grp;
                af[mt][0] = As[s][mr][kb + tig];
                af[mt][1] = As[s][mr + 8][kb + tig];
                af[mt][2] = As[s][mr][kb + tig + 4];
                af[mt][3] = As[s][mr + 8][kb + tig + 4];
            }
#pragma unroll
            for (int nt = 0; nt < 8; nt++) {
                const int nc = wn * 64 + nt * 8 + grp;
                bf[nt][0] = Bs[s][kb + tig][nc];
                bf[nt][1] = Bs[s][kb + tig + 4][nc];
            }
#pragma unroll
            for (int mt = 0; mt < 2; mt++)
#pragma unroll
                for (int nt = 0; nt < 8; nt++)
                    mma_tf32(acc[mt][nt], af[mt], bf[nt]);
        }

        // issue loads for stage ks+2
        if (ks + STAGES - 1 < nk) {
            const int so = (ks + STAGES - 1) % STAGES;
            const int k0 = (ks + STAGES - 1) << 4;
            cpasync16(&As[so][a_row][a_kc],      Abase + (size_t)a_row * K + k0 + a_kc);
            cpasync16(&As[so][a_row + 64][a_kc], Abase + (size_t)(a_row + 64) * K + k0 + a_kc);
            cpasync16(&Bs[so][b_k][b_n4],        Bbase + (size_t)(k0 + b_k) * N + b_n4);
            cpasync16(&Bs[so][b_k + 8][b_n4],    Bbase + (size_t)(k0 + b_k + 8) * N + b_n4);
        }
        cpasync_commit();
    }

    // epilogue
#pragma unroll
    for (int mt = 0; mt < 2; mt++) {
        const int row0 = by * 128 + wm * 32 + mt * 16 + grp;
#pragma unroll
        for (int nt = 0; nt < 8; nt++) {
            const int col = bx * 128 + wn * 64 + nt * 8 + tig * 2;
            if (MODE == 0) {
#pragma unroll
                for (int half = 0; half < 2; half++) {
                    const int row = row0 + half * 8;
                    const int bb = row >> 11;
                    const int t  = row & 2047;
                    const int which = col >> 11;
                    const int c = col & 2047;
                    const int h = c >> 7;
                    const int dd = c & 127;
                    float* base = (which == 0) ? g_q : (which == 1) ? g_k : g_v;
                    float* dst = base + ((size_t)(bb * NH + h) * TT + t) * HD + dd;
                    float v0 = acc[mt][nt][half * 2];
                    float v1 = acc[mt][nt][half * 2 + 1];
                    if (which == 2) { v0 = f2tf_f(v0); v1 = f2tf_f(v1); }
                    *(float2*)dst = make_float2(v0, v1);
                }
            } else {
                *(float2*)(Cp + (size_t)row0 * N + col) =
                    make_float2(acc[mt][nt][0], acc[mt][nt][1]);
                *(float2*)(Cp + (size_t)(row0 + 8) * N + col) =
                    make_float2(acc[mt][nt][2], acc[mt][nt][3]);
            }
        }
    }
}

// ---------------------------------------------------------------------------
// RoPE kernel: rotate q,k in place and pre-round to tf32 bits.
// ---------------------------------------------------------------------------
__global__ void rope_kernel(const float* __restrict__ cosp,
                            const float* __restrict__ sinp)
{
    int row = blockIdx.x;
    int t = row & (TT - 1);
    int tid = threadIdx.x;
    int d = tid & 63;
    float* arr = (tid < 64) ? g_q : g_k;
    float* base = arr + (size_t)row * HD;
    float c = cosp[t*64 + d];
    float s = sinp[t*64 + d];
    float x1 = base[d];
    float x2 = base[d + 64];
    base[d]      = f2tf_f(x1*c - x2*s);
    base[d + 64] = f2tf_f(x1*s + x2*c);
}

// ---------------------------------------------------------------------------
// Flash attention: TF32 MMA, Br=128 (8 warps x 16 rows), Bc=64.
// ---------------------------------------------------------------------------
#define FBR 128
#define FBC 64
#define FKS 132
#define FPS 68
#define FLASH2_SMEM ((FBR*FKS + 2*FBC*FKS + 8*16*FPS) * 4)

__global__ void __launch_bounds__(256)
flash2_kernel()
{
    extern __shared__ unsigned sm[];
    unsigned* uQ = sm;
    unsigned* uK = uQ + FBR*FKS;
    unsigned* uV = uK + FBC*FKS;
    unsigned* uP = uV + FBC*FKS;

    const int qt  = blockIdx.x;
    const int bh  = blockIdx.y;
    const int tid = threadIdx.x;
    const int lane = tid & 31;
    const int wq   = tid >> 5;
    const int tig  = lane & 3;
    const int grp  = lane >> 4;
    const int grp_ = lane >> 2;

    // load Q tile (already tf32 bits)
    {
        const float* Qg = g_q + ((size_t)bh*TT + qt*FBR)*HD;
#pragma unroll
        for (int i = 0; i < FBR*HD/4/256; i++) {
            int lin = tid + i*256;
            int r  = lin >> 5;
            int c4 = (lin & 31) * 4;
            *(float4*)&uQ[r*FKS + c4] = *(const float4*)(Qg + (size_t)r*HD + c4);
        }
    }

    float m_i[2], l_i[2];
    m_i[0] = m_i[1] = -1e30f;
    l_i[0] = l_i[1] = 0.f;
    float oc[16][4];
#pragma unroll
    for (int n = 0; n < 16; n++)
#pragma unroll
        for (int r = 0; r < 4; r++) oc[n][r] = 0.f;

    const float scale = 0.08838834764831845f;
    const int warp_row0 = qt*FBR + wq*16;
    const int nblocks = 2*qt + 2;

    for (int jc = 0; jc < nblocks; jc++) {
        __syncthreads();
        {
            const float* Kg = g_k + ((size_t)bh*TT + jc*FBC)*HD;
            const float* Vg = g_v + ((size_t)bh*TT + jc*FBC)*HD;
#pragma unroll
            for (int i = 0; i < FBC*HD/4/256; i++) {
                int lin = tid + i*256;
                int r  = lin >> 5;
                int c4 = (lin & 31) * 4;
                *(float4*)&uK[r*FKS + c4] = *(const float4*)(Kg + (size_t)r*HD + c4);
                *(float4*)&uV[r*FKS + c4] = *(const float4*)(Vg + (size_t)r*HD + c4);
            }
        }
        __syncthreads();

        if (jc*FBC > warp_row0 + 15) continue;

        // ---- S = Q K^T ----
        float sc[8][4];
#pragma unroll
        for (int n = 0; n < 8; n++)
#pragma unroll
            for (int r = 0; r < 4; r++) sc[n][r] = 0.f;

#pragma unroll
        for (int ks = 0; ks < 16; ks++) {
            const int d0 = ks*8;
            unsigned af[4];
            af[0] = uQ[(wq*16 + grp_    )*FKS + d0 + tig];
            af[1] = uQ[(wq*16 + grp_ + 8)*FKS + d0 + tig];
            af[2] = uQ[(wq*16 + grp_    )*FKS + d0 + tig + 4];
            af[3] = uQ[(wq*16 + grp_ + 8)*FKS + d0 + tig + 4];
#pragma unroll
            for (int nt = 0; nt < 8; nt++) {
                unsigned bf[2];
                bf[0] = uK[(nt*8 + grp_)*FKS + d0 + tig];
                bf[1] = uK[(nt*8 + grp_)*FKS + d0 + tig + 4];
                mma_tf32(sc[nt], af, bf);
            }
        }

        // ---- online softmax ----
        unsigned* Pw = uP + wq*16*FPS;
#pragma unroll
        for (int h = 0; h < 2; h++) {
            const int row = warp_row0 + grp_ + h*8;
            float rmax = -1e30f;
#pragma unroll
            for (int nt = 0; nt < 8; nt++) {
#pragma unroll
                for (int c = 0; c < 2; c++) {
                    const int col = jc*FBC + nt*8 + tig*2 + c;
                    float v = sc[nt][h*2 + c] * scale;
                    if (col > row) v = -1e30f;
                    sc[nt][h*2 + c] = v;
                    rmax = fmaxf(rmax, v);
                }
            }
            rmax = fmaxf(rmax, __shfl_xor_sync(0xffffffffu, rmax, 1));
            rmax = fmaxf(rmax, __shfl_xor_sync(0xffffffffu, rmax, 2));

            const float m_new = fmaxf(m_i[h], rmax);
            const float fac = __expf(m_i[h] - m_new);
            float rsum = 0.f;
#pragma unroll
            for (int nt = 0; nt < 8; nt++) {
#pragma unroll
                for (int c = 0; c < 2; c++) {
                    float p = __expf(sc[nt][h*2 + c] - m_new);
                    sc[nt][h*2 + c] = p;
                    rsum += p;
                    Pw[(grp_ + h*8)*FPS + nt*8 + tig*2 + c] = f2tf(p);
                }
            }
            rsum += __shfl_xor_sync(0xffffffffu, rsum, 1);
            rsum += __shfl_xor_sync(0xffffffffu, rsum, 2);

            l_i[h] = l_i[h]*fac + rsum;
            m_i[h] = m_new;
#pragma unroll
            for (int nt = 0; nt < 16; nt++) {
                oc[nt][h*2]     *= fac;
                oc[nt][h*2 + 1] *= fac;
            }
        }
        __syncwarp();

        // ---- O += P V ----
#pragma unroll
        for (int k0 = 0; k0 < FBC; k0 += 8) {
            unsigned af[4];
            af[0] = Pw[(grp_    )*FPS + k0 + tig];
            af[1] = Pw[(grp_ + 8)*FPS + k0 + tig];
            af[2] = Pw[(grp_    )*FPS + k0 + tig + 4];
            af[3] = Pw[(grp_ + 8)*FPS + k0 + tig + 4];
#pragma unroll
            for (int nt = 0; nt < 16; nt++) {
                unsigned bf[2];
                bf[0] = uV[(k0 + tig    )*FKS + nt*8 + grp_];
                bf[1] = uV[(k0 + tig + 4)*FKS + nt*8 + grp_];
                mma_tf32(oc[nt], af, bf);
            }
        }
    }

    // epilogue: y pre-rounded for gemm<1>
    const int b = bh >> 4;
    const int h = bh & 15;
#pragma unroll
    for (int hh = 0; hh < 2; hh++) {
        const int t = qt*FBR + wq*16 + grp_ + hh*8;
        const float inv = 1.f / l_i[hh];
        float* yrow = g_y + ((size_t)(b*TT + t))*CC + h*HD;
#pragma unroll
        for (int nt = 0; nt < 16; nt++) {
            *(float2*)(yrow + nt*8 + tig*2) =
                make_float2(f2tf_f(oc[nt][hh*2] * inv),
                            f2tf_f(oc[nt][hh*2 + 1] * inv));
        }
    }
}

// ---------------------------------------------------------------------------
// launch
// ---------------------------------------------------------------------------
extern "C" void kernel_launch(void* const* d_in, const int* in_sizes, int n_in,
                              void* d_out, int out_size)
{
    const float* x    = (const float*)d_in[0];
    const float* cosp = (const float*)d_in[1];
    const float* sinp = (const float*)d_in[2];
    const float* Wa   = (const float*)d_in[3];
    const float* Wp   = (const float*)d_in[4];
    float* out = (float*)d_out;

    float *dx, *dwa, *dwp;
    cudaGetSymbolAddress((void**)&dx,  g_x);
    cudaGetSymbolAddress((void**)&dwa, g_wa);
    cudaGetSymbolAddress((void**)&dwp, g_wp);

    // 0) pre-round operands to tf32 bits
    cvt_tf32_kernel<<<2048, 256>>>((const float4*)x,  (float4*)dx,  MM*CC/4);
    cvt_tf32_kernel<<<2048, 256>>>((const float4*)Wa, (float4*)dwa, CC*N_QKV/4);
    cvt_tf32_kernel<<<2048, 256>>>((const float4*)Wp, (float4*)dwp, CC*CC/4);

    // 1) qkv = x @ W_attn -> head-major q/k/v
    gemm_tf32<0><<<dim3(N_QKV/128, MM/128), 256>>>(nullptr, MM, N_QKV, CC);

    // 2) RoPE on q,k (writes tf32-rounded)
    rope_kernel<<<BB*NH*TT, 128>>>(cosp, sinp);

    // 3) flash attention -> g_y (tf32-rounded)
    cudaFuncSetAttribute(flash2_kernel, cudaFuncAttributeMaxDynamicSharedMemorySize,
                         (int)FLASH2_SMEM);
    flash2_kernel<<<dim3(TT/FBR, BB*NH), 256, FLASH2_SMEM>>>();

    // 4) out = y @ W_proj
    gemm_tf32<1><<<dim3(CC/128, MM/128), 256>>>(out, MM, CC, CC);
}

// round 6
// speedup vs baseline: 6.9301x; 1.0553x over previous
#include <cuda_runtime.h>
#include <cuda_bf16.h>
#include <math.h>

// Problem constants
#define BB   2
#define TT   2048
#define CC   2048
#define NH   16
#define HD   128
#define MM   (BB*TT)        // 4096
#define N_QKV (3*CC)        // 6144

// ---------------------------------------------------------------------------
// Scratch (device globals; no runtime allocation)
// ---------------------------------------------------------------------------
__device__ float g_q[(size_t)BB*NH*TT*HD];   // [B,H,T,hd], q pre-scaled
__device__ float g_k[(size_t)BB*NH*TT*HD];
__device__ float g_v[(size_t)BB*NH*TT*HD];   // pre-rounded tf32 bits
__device__ float g_y[(size_t)BB*TT*CC];      // pre-rounded tf32 bits
__device__ float g_x[(size_t)MM*CC];         // pre-rounded x
__device__ float g_wa[(size_t)CC*N_QKV];     // pre-rounded W_attn^T  [N_QKV][CC]
__device__ float g_wp[(size_t)CC*CC];        // pre-rounded W_proj^T  [CC][CC]

// ---------------------------------------------------------------------------
// TF32 / math helpers
// ---------------------------------------------------------------------------
__device__ __forceinline__ unsigned f2tf(float x) {
    unsigned r;
    asm("cvt.rna.tf32.f32 %0, %1;" : "=r"(r) : "f"(x));
    return r;
}
__device__ __forceinline__ float f2tf_f(float x) {
    return __uint_as_float(f2tf(x));
}
__device__ __forceinline__ float ex2(float x) {
    float y;
    asm("ex2.approx.f32 %0, %1;" : "=f"(y) : "f"(x));
    return y;
}

__device__ __forceinline__ void mma_tf32(float* c, const unsigned* a, const unsigned* b) {
    asm volatile(
        "mma.sync.aligned.m16n8k8.row.col.f32.tf32.tf32.f32 "
        "{%0,%1,%2,%3}, {%4,%5,%6,%7}, {%8,%9}, {%0,%1,%2,%3};"
        : "+f"(c[0]), "+f"(c[1]), "+f"(c[2]), "+f"(c[3])
        : "r"(a[0]), "r"(a[1]), "r"(a[2]), "r"(a[3]),
          "r"(b[0]), "r"(b[1]));
}

__device__ __forceinline__ void ldsm4(unsigned* r, unsigned addr) {
    asm volatile("ldmatrix.sync.aligned.m8n8.x4.shared.b16 {%0,%1,%2,%3}, [%4];"
        : "=r"(r[0]), "=r"(r[1]), "=r"(r[2]), "=r"(r[3]) : "r"(addr));
}

// cp.async helpers
__device__ __forceinline__ void cpasync16(void* smem_dst, const void* gsrc) {
    unsigned s = (unsigned)__cvta_generic_to_shared(smem_dst);
    asm volatile("cp.async.cg.shared.global [%0], [%1], 16;\n" :: "r"(s), "l"(gsrc));
}
__device__ __forceinline__ void cpasync_commit() {
    asm volatile("cp.async.commit_group;\n");
}
template <int N>
__device__ __forceinline__ void cpasync_wait() {
    asm volatile("cp.async.wait_group %0;\n" :: "n"(N));
}

// ---------------------------------------------------------------------------
// Pre-round fp32 -> tf32 bits (elementwise, float4 grid-stride) — for x
// ---------------------------------------------------------------------------
__global__ void cvt_tf32_kernel(const float4* __restrict__ in,
                                float4* __restrict__ out, int n4)
{
    for (int i = blockIdx.x * blockDim.x + threadIdx.x; i < n4;
         i += gridDim.x * blockDim.x) {
        float4 v = in[i];
        v.x = f2tf_f(v.x); v.y = f2tf_f(v.y); v.z = f2tf_f(v.z); v.w = f2tf_f(v.w);
        out[i] = v;
    }
}

// ---------------------------------------------------------------------------
// Transpose + pre-round: out[n][k] = tf32(in[k][n]).  in: [K][N]
// ---------------------------------------------------------------------------
__global__ void cvt_t_kernel(const float* __restrict__ in,
                             float* __restrict__ out, int K, int N)
{
    __shared__ float tile[32][33];
    const int k0 = blockIdx.y * 32;
    const int n0 = blockIdx.x * 32;
#pragma unroll
    for (int i = threadIdx.y; i < 32; i += 8)
        tile[i][threadIdx.x] = in[(size_t)(k0 + i) * N + n0 + threadIdx.x];
    __syncthreads();
#pragma unroll
    for (int i = threadIdx.y; i < 32; i += 8)
        out[(size_t)(n0 + i) * K + k0 + threadIdx.x] = f2tf_f(tile[threadIdx.x][i]);
}

// ---------------------------------------------------------------------------
// TF32 GEMM, B pre-transposed.  C = A[M,K] @ B'[N,K]^T
// 128x128 tile, BK=16, cp.async 3-stage, 2 CTAs/SM, ldmatrix fragment loads.
// 8 warps (4M x 2N), warp tile 32x64.
// MODE 0: A=g_x, B=g_wa, epilogue scatters into g_q/g_k/g_v
// MODE 1: A=g_y, B=g_wp, epilogue writes row-major C (d_out)
// ---------------------------------------------------------------------------
#define ASTR 20
#define STAGES 3

template <int MODE>
__global__ void __launch_bounds__(256, 2)
gemm_tf32(float* __restrict__ Cp, int M, int N, int K)
{
    __shared__ unsigned As[STAGES][128][ASTR];
    __shared__ unsigned Bs[STAGES][128][ASTR];

    const float* A = (MODE == 0) ? g_x : g_y;
    const float* B = (MODE == 0) ? g_wa : g_wp;   // [N][K]

    const int bx = blockIdx.x;
    const int by = blockIdx.y;
    const int tid  = threadIdx.x;
    const int lane = tid & 31;
    const int warp = tid >> 5;
    const int wm = warp >> 1;
    const int wn = warp & 1;
    const int tig = lane & 3;
    const int grp = lane >> 2;

    // cp.async load indexing (same pattern for A and B)
    const int l_row = tid >> 2;          // 0..63 (and +64)
    const int l_kc  = (tid & 3) * 4;

    const float* Abase = A + (size_t)(by * 128) * K;
    const float* Bbase = B + (size_t)(bx * 128) * K;

    // ldmatrix lane offsets
    const int g8 = lane >> 3;            // tile group 0..3
    const int r8 = lane & 7;             // row within tile
    const int a_ro = (g8 & 1) * 8 + r8;  // A: row offset, col sel by g8>>1
    const int a_co = (g8 >> 1) * 4;
    const int b_ro = (g8 >> 1) * 8 + r8; // B: row offset, col sel by g8&1
    const int b_co = (g8 & 1) * 4;

    unsigned asb[STAGES], bsb[STAGES];
#pragma unroll
    for (int p = 0; p < STAGES; p++) {
        asb[p] = (unsigned)__cvta_generic_to_shared(&As[p][0][0]);
        bsb[p] = (unsigned)__cvta_generic_to_shared(&Bs[p][0][0]);
    }

    float acc[2][8][4];
#pragma unroll
    for (int i = 0; i < 2; i++)
#pragma unroll
        for (int j = 0; j < 8; j++)
#pragma unroll
            for (int r = 0; r < 4; r++) acc[i][j][r] = 0.f;

    const int nk = K >> 4;

    // pipeline prologue
#pragma unroll
    for (int p = 0; p < STAGES - 1; p++) {
        const int k0 = p << 4;
        cpasync16(&As[p][l_row][l_kc],      Abase + (size_t)l_row * K + k0 + l_kc);
        cpasync16(&As[p][l_row + 64][l_kc], Abase + (size_t)(l_row + 64) * K + k0 + l_kc);
        cpasync16(&Bs[p][l_row][l_kc],      Bbase + (size_t)l_row * K + k0 + l_kc);
        cpasync16(&Bs[p][l_row + 64][l_kc], Bbase + (size_t)(l_row + 64) * K + k0 + l_kc);
        cpasync_commit();
    }

    for (int ks = 0; ks < nk; ks++) {
        const int s = ks % STAGES;
        cpasync_wait<STAGES - 2>();
        __syncthreads();

#pragma unroll
        for (int kk = 0; kk < 2; kk++) {
            const int kb = kk * 8;
            unsigned af[2][4], bf[8][2];
#pragma unroll
            for (int mt = 0; mt < 2; mt++) {
                unsigned addr = asb[s] +
                    ((wm*32 + mt*16 + a_ro) * ASTR + kb + a_co) * 4;
                ldsm4(af[mt], addr);
            }
#pragma unroll
            for (int ntp = 0; ntp < 4; ntp++) {
                unsigned bq[4];
                unsigned addr = bsb[s] +
                    ((wn*64 + ntp*16 + b_ro) * ASTR + kb + b_co) * 4;
                ldsm4(bq, addr);
                bf[2*ntp][0]   = bq[0]; bf[2*ntp][1]   = bq[1];
                bf[2*ntp+1][0] = bq[2]; bf[2*ntp+1][1] = bq[3];
            }
#pragma unroll
            for (int mt = 0; mt < 2; mt++)
#pragma unroll
                for (int nt = 0; nt < 8; nt++)
                    mma_tf32(acc[mt][nt], af[mt], bf[nt]);
        }

        if (ks + STAGES - 1 < nk) {
            const int so = (ks + STAGES - 1) % STAGES;
            const int k0 = (ks + STAGES - 1) << 4;
            cpasync16(&As[so][l_row][l_kc],      Abase + (size_t)l_row * K + k0 + l_kc);
            cpasync16(&As[so][l_row + 64][l_kc], Abase + (size_t)(l_row + 64) * K + k0 + l_kc);
            cpasync16(&Bs[so][l_row][l_kc],      Bbase + (size_t)l_row * K + k0 + l_kc);
            cpasync16(&Bs[so][l_row + 64][l_kc], Bbase + (size_t)(l_row + 64) * K + k0 + l_kc);
        }
        cpasync_commit();
    }

    // epilogue
#pragma unroll
    for (int mt = 0; mt < 2; mt++) {
        const int row0 = by * 128 + wm * 32 + mt * 16 + grp;
#pragma unroll
        for (int nt = 0; nt < 8; nt++) {
            const int col = bx * 128 + wn * 64 + nt * 8 + tig * 2;
            if (MODE == 0) {
#pragma unroll
                for (int half = 0; half < 2; half++) {
                    const int row = row0 + half * 8;
                    const int bb = row >> 11;
                    const int t  = row & 2047;
                    const int which = col >> 11;
                    const int c = col & 2047;
                    const int h = c >> 7;
                    const int dd = c & 127;
                    float* base = (which == 0) ? g_q : (which == 1) ? g_k : g_v;
                    float* dst = base + ((size_t)(bb * NH + h) * TT + t) * HD + dd;
                    float v0 = acc[mt][nt][half * 2];
                    float v1 = acc[mt][nt][half * 2 + 1];
                    if (which == 2) { v0 = f2tf_f(v0); v1 = f2tf_f(v1); }
                    *(float2*)dst = make_float2(v0, v1);
                }
            } else {
                *(float2*)(Cp + (size_t)row0 * N + col) =
                    make_float2(acc[mt][nt][0], acc[mt][nt][1]);
                *(float2*)(Cp + (size_t)(row0 + 8) * N + col) =
                    make_float2(acc[mt][nt][2], acc[mt][nt][3]);
            }
        }
    }
}

// ---------------------------------------------------------------------------
// RoPE: rotate q,k in place, pre-round to tf32.
// q additionally scaled by (1/sqrt(hd))*log2(e) so flash softmax works in
// log2 domain with no per-element multiplies.
// ---------------------------------------------------------------------------
#define QSCALE (0.08838834764831845f * 1.4426950408889634f)

__global__ void rope_kernel(const float* __restrict__ cosp,
                            const float* __restrict__ sinp)
{
    int row = blockIdx.x;
    int t = row & (TT - 1);
    int tid = threadIdx.x;
    int d = tid & 63;
    bool isq = (tid < 64);
    float* arr = isq ? g_q : g_k;
    float sc = isq ? QSCALE : 1.f;
    float* base = arr + (size_t)row * HD;
    float c = cosp[t*64 + d];
    float s = sinp[t*64 + d];
    float x1 = base[d];
    float x2 = base[d + 64];
    base[d]      = f2tf_f((x1*c - x2*s) * sc);
    base[d + 64] = f2tf_f((x1*s + x2*c) * sc);
}

// ---------------------------------------------------------------------------
// Flash attention: TF32 MMA, Br=128 (8 warps x 16 rows), Bc=64.
// Scores already in log2 domain (q pre-scaled); ex2.approx softmax;
// causal mask only on diagonal blocks.
// ---------------------------------------------------------------------------
#define FBR 128
#define FBC 64
#define FKS 132
#define FPS 68
#define FLASH2_SMEM ((FBR*FKS + 2*FBC*FKS + 8*16*FPS) * 4)

__global__ void __launch_bounds__(256)
flash2_kernel()
{
    extern __shared__ unsigned sm[];
    unsigned* uQ = sm;
    unsigned* uK = uQ + FBR*FKS;
    unsigned* uV = uK + FBC*FKS;
    unsigned* uP = uV + FBC*FKS;

    const int qt  = blockIdx.x;
    const int bh  = blockIdx.y;
    const int tid = threadIdx.x;
    const int lane = tid & 31;
    const int wq   = tid >> 5;
    const int tig  = lane & 3;
    const int grp  = lane >> 2;

    // load Q tile (tf32 bits, pre-scaled)
    {
        const float* Qg = g_q + ((size_t)bh*TT + qt*FBR)*HD;
#pragma unroll
        for (int i = 0; i < FBR*HD/4/256; i++) {
            int lin = tid + i*256;
            int r  = lin >> 5;
            int c4 = (lin & 31) * 4;
            *(float4*)&uQ[r*FKS + c4] = *(const float4*)(Qg + (size_t)r*HD + c4);
        }
    }

    float m_i[2], l_i[2];
    m_i[0] = m_i[1] = -1e30f;
    l_i[0] = l_i[1] = 0.f;
    float oc[16][4];
#pragma unroll
    for (int n = 0; n < 16; n++)
#pragma unroll
        for (int r = 0; r < 4; r++) oc[n][r] = 0.f;

    const int warp_row0 = qt*FBR + wq*16;
    const int nblocks = 2*qt + 2;

    for (int jc = 0; jc < nblocks; jc++) {
        __syncthreads();
        {
            const float* Kg = g_k + ((size_t)bh*TT + jc*FBC)*HD;
            const float* Vg = g_v + ((size_t)bh*TT + jc*FBC)*HD;
#pragma unroll
            for (int i = 0; i < FBC*HD/4/256; i++) {
                int lin = tid + i*256;
                int r  = lin >> 5;
                int c4 = (lin & 31) * 4;
                *(float4*)&uK[r*FKS + c4] = *(const float4*)(Kg + (size_t)r*HD + c4);
                *(float4*)&uV[r*FKS + c4] = *(const float4*)(Vg + (size_t)r*HD + c4);
            }
        }
        __syncthreads();

        if (jc*FBC > warp_row0 + 15) continue;
        const bool diag = (jc*FBC + FBC - 1) > warp_row0;

        // ---- S = Q K^T  (scores in log2 units) ----
        float sc[8][4];
#pragma unroll
        for (int n = 0; n < 8; n++)
#pragma unroll
            for (int r = 0; r < 4; r++) sc[n][r] = 0.f;

#pragma unroll
        for (int ks = 0; ks < 16; ks++) {
            const int d0 = ks*8;
            unsigned af[4];
            af[0] = uQ[(wq*16 + grp    )*FKS + d0 + tig];
            af[1] = uQ[(wq*16 + grp + 8)*FKS + d0 + tig];
            af[2] = uQ[(wq*16 + grp    )*FKS + d0 + tig + 4];
            af[3] = uQ[(wq*16 + grp + 8)*FKS + d0 + tig + 4];
#pragma unroll
            for (int nt = 0; nt < 8; nt++) {
                unsigned bf[2];
                bf[0] = uK[(nt*8 + grp)*FKS + d0 + tig];
                bf[1] = uK[(nt*8 + grp)*FKS + d0 + tig + 4];
                mma_tf32(sc[nt], af, bf);
            }
        }

        // ---- online softmax (log2 domain) ----
        unsigned* Pw = uP + wq*16*FPS;
#pragma unroll
        for (int h = 0; h < 2; h++) {
            const int row = warp_row0 + grp + h*8;
            float rmax = -1e30f;
            if (diag) {
#pragma unroll
                for (int nt = 0; nt < 8; nt++)
#pragma unroll
                    for (int c = 0; c < 2; c++) {
                        const int col = jc*FBC + nt*8 + tig*2 + c;
                        float v = sc[nt][h*2 + c];
                        if (col > row) v = -1e30f;
                        sc[nt][h*2 + c] = v;
                        rmax = fmaxf(rmax, v);
                    }
            } else {
#pragma unroll
                for (int nt = 0; nt < 8; nt++) {
                    rmax = fmaxf(rmax, fmaxf(sc[nt][h*2], sc[nt][h*2 + 1]));
                }
            }
            rmax = fmaxf(rmax, __shfl_xor_sync(0xffffffffu, rmax, 1));
            rmax = fmaxf(rmax, __shfl_xor_sync(0xffffffffu, rmax, 2));

            const float m_new = fmaxf(m_i[h], rmax);
            const float fac = ex2(m_i[h] - m_new);
            float rsum = 0.f;
#pragma unroll
            for (int nt = 0; nt < 8; nt++) {
#pragma unroll
                for (int c = 0; c < 2; c++) {
                    float p = ex2(sc[nt][h*2 + c] - m_new);
                    rsum += p;
                    Pw[(grp + h*8)*FPS + nt*8 + tig*2 + c] = f2tf(p);
                }
            }
            rsum += __shfl_xor_sync(0xffffffffu, rsum, 1);
            rsum += __shfl_xor_sync(0xffffffffu, rsum, 2);

            l_i[h] = l_i[h]*fac + rsum;
            m_i[h] = m_new;
#pragma unroll
            for (int nt = 0; nt < 16; nt++) {
                oc[nt][h*2]     *= fac;
                oc[nt][h*2 + 1] *= fac;
            }
        }
        __syncwarp();

        // ---- O += P V ----
#pragma unroll
        for (int k0 = 0; k0 < FBC; k0 += 8) {
            unsigned af[4];
            af[0] = Pw[(grp    )*FPS + k0 + tig];
            af[1] = Pw[(grp + 8)*FPS + k0 + tig];
            af[2] = Pw[(grp    )*FPS + k0 + tig + 4];
            af[3] = Pw[(grp + 8)*FPS + k0 + tig + 4];
#pragma unroll
            for (int nt = 0; nt < 16; nt++) {
                unsigned bf[2];
                bf[0] = uV[(k0 + tig    )*FKS + nt*8 + grp];
                bf[1] = uV[(k0 + tig + 4)*FKS + nt*8 + grp];
                mma_tf32(oc[nt], af, bf);
            }
        }
    }

    // epilogue: y pre-rounded for gemm<1>
    const int b = bh >> 4;
    const int h = bh & 15;
#pragma unroll
    for (int hh = 0; hh < 2; hh++) {
        const int t = qt*FBR + wq*16 + grp + hh*8;
        const float inv = 1.f / l_i[hh];
        float* yrow = g_y + ((size_t)(b*TT + t))*CC + h*HD;
#pragma unroll
        for (int nt = 0; nt < 16; nt++) {
            *(float2*)(yrow + nt*8 + tig*2) =
                make_float2(f2tf_f(oc[nt][hh*2] * inv),
                            f2tf_f(oc[nt][hh*2 + 1] * inv));
        }
    }
}

// ---------------------------------------------------------------------------
// launch
// ---------------------------------------------------------------------------
extern "C" void kernel_launch(void* const* d_in, const int* in_sizes, int n_in,
                              void* d_out, int out_size)
{
    const float* x    = (const float*)d_in[0];
    const float* cosp = (const float*)d_in[1];
    const float* sinp = (const float*)d_in[2];
    const float* Wa   = (const float*)d_in[3];
    const float* Wp   = (const float*)d_in[4];
    float* out = (float*)d_out;

    float *dx, *dwa, *dwp;
    cudaGetSymbolAddress((void**)&dx,  g_x);
    cudaGetSymbolAddress((void**)&dwa, g_wa);
    cudaGetSymbolAddress((void**)&dwp, g_wp);

    // 0) pre-round x; transpose + pre-round weights
    cvt_tf32_kernel<<<2048, 256>>>((const float4*)x, (float4*)dx, MM*CC/4);
    cvt_t_kernel<<<dim3(N_QKV/32, CC/32), dim3(32, 8)>>>(Wa, dwa, CC, N_QKV);
    cvt_t_kernel<<<dim3(CC/32,   CC/32), dim3(32, 8)>>>(Wp, dwp, CC, CC);

    // 1) qkv = x @ W_attn -> head-major q/k/v
    gemm_tf32<0><<<dim3(N_QKV/128, MM/128), 256>>>(nullptr, MM, N_QKV, CC);

    // 2) RoPE on q,k (q pre-scaled by 1/sqrt(hd)*log2e, tf32-rounded)
    rope_kernel<<<BB*NH*TT, 128>>>(cosp, sinp);

    // 3) flash attention -> g_y (tf32-rounded)
    cudaFuncSetAttribute(flash2_kernel, cudaFuncAttributeMaxDynamicSharedMemorySize,
                         (int)FLASH2_SMEM);
    flash2_kernel<<<dim3(TT/FBR, BB*NH), 256, FLASH2_SMEM>>>();

    // 4) out = y @ W_proj
    gemm_tf32<1><<<dim3(CC/128, MM/128), 256>>>(out, MM, CC, CC);
}

// round 9
// speedup vs baseline: 7.4849x; 1.0801x over previous
#include <cuda_runtime.h>
#include <cuda_bf16.h>
#include <math.h>

// Problem constants
#define BB   2
#define TT   2048
#define CC   2048
#define NH   16
#define HD   128
#define MM   (BB*TT)        // 4096
#define N_QKV (3*CC)        // 6144

// ---------------------------------------------------------------------------
// Scratch (device globals; no runtime allocation)
// ---------------------------------------------------------------------------
__device__ float g_q[(size_t)BB*NH*TT*HD];   // [B,H,T,hd], q pre-scaled, tf32 bits
__device__ float g_k[(size_t)BB*NH*TT*HD];   // tf32 bits
__device__ float g_v[(size_t)BB*NH*TT*HD];   // tf32 bits
__device__ float g_y[(size_t)BB*TT*CC];      // tf32 bits
__device__ float g_x[(size_t)MM*CC];         // tf32 bits
__device__ float g_wa[(size_t)CC*N_QKV];     // tf32 bits, W_attn^T [N_QKV][CC]
__device__ float g_wp[(size_t)CC*CC];        // tf32 bits, W_proj^T [CC][CC]

// ---------------------------------------------------------------------------
// TF32 / math helpers
// ---------------------------------------------------------------------------
__device__ __forceinline__ unsigned f2tf(float x) {
    unsigned r;
    asm("cvt.rna.tf32.f32 %0, %1;" : "=r"(r) : "f"(x));
    return r;
}
__device__ __forceinline__ float f2tf_f(float x) {
    return __uint_as_float(f2tf(x));
}
__device__ __forceinline__ float ex2(float x) {
    float y;
    asm("ex2.approx.f32 %0, %1;" : "=f"(y) : "f"(x));
    return y;
}

__device__ __forceinline__ void mma_tf32(float* c, const unsigned* a, const unsigned* b) {
    asm volatile(
        "mma.sync.aligned.m16n8k8.row.col.f32.tf32.tf32.f32 "
        "{%0,%1,%2,%3}, {%4,%5,%6,%7}, {%8,%9}, {%0,%1,%2,%3};"
        : "+f"(c[0]), "+f"(c[1]), "+f"(c[2]), "+f"(c[3])
        : "r"(a[0]), "r"(a[1]), "r"(a[2]), "r"(a[3]),
          "r"(b[0]), "r"(b[1]));
}

__device__ __forceinline__ void ldsm4(unsigned* r, unsigned addr) {
    asm volatile("ldmatrix.sync.aligned.m8n8.x4.shared.b16 {%0,%1,%2,%3}, [%4];"
        : "=r"(r[0]), "=r"(r[1]), "=r"(r[2]), "=r"(r[3]) : "r"(addr));
}

// cp.async helpers
__device__ __forceinline__ void cpasync16(void* smem_dst, const void* gsrc) {
    unsigned s = (unsigned)__cvta_generic_to_shared(smem_dst);
    asm volatile("cp.async.cg.shared.global [%0], [%1], 16;\n" :: "r"(s), "l"(gsrc));
}
__device__ __forceinline__ void cpasync_commit() {
    asm volatile("cp.async.commit_group;\n");
}
template <int N>
__device__ __forceinline__ void cpasync_wait() {
    asm volatile("cp.async.wait_group %0;\n" :: "n"(N));
}

// ---------------------------------------------------------------------------
// Pre-round fp32 -> tf32 bits (elementwise, float4 grid-stride) — for x
// ---------------------------------------------------------------------------
__global__ void cvt_tf32_kernel(const float4* __restrict__ in,
                                float4* __restrict__ out, int n4)
{
    for (int i = blockIdx.x * blockDim.x + threadIdx.x; i < n4;
         i += gridDim.x * blockDim.x) {
        float4 v = in[i];
        v.x = f2tf_f(v.x); v.y = f2tf_f(v.y); v.z = f2tf_f(v.z); v.w = f2tf_f(v.w);
        out[i] = v;
    }
}

// ---------------------------------------------------------------------------
// Transpose + pre-round: out[n][k] = tf32(in[k][n]).  in: [K][N]
// ---------------------------------------------------------------------------
__global__ void cvt_t_kernel(const float* __restrict__ in,
                             float* __restrict__ out, int K, int N)
{
    __shared__ float tile[32][33];
    const int k0 = blockIdx.y * 32;
    const int n0 = blockIdx.x * 32;
#pragma unroll
    for (int i = threadIdx.y; i < 32; i += 8)
        tile[i][threadIdx.x] = in[(size_t)(k0 + i) * N + n0 + threadIdx.x];
    __syncthreads();
#pragma unroll
    for (int i = threadIdx.y; i < 32; i += 8)
        out[(size_t)(n0 + i) * K + k0 + threadIdx.x] = f2tf_f(tile[threadIdx.x][i]);
}

// ---------------------------------------------------------------------------
// TF32 GEMM, B pre-transposed.  C = A[M,K] @ B'[N,K]^T
// 128x128 tile, BK=32, cp.async 3-stage, 2 CTAs/SM, ldmatrix fragment loads.
// 8 warps (4M x 2N), warp tile 32x64.  Dynamic smem.
// MODE 0: A=g_x, B=g_wa, epilogue scatters into g_q/g_k/g_v
// MODE 1: A=g_y, B=g_wp, epilogue writes row-major C (d_out)
// ---------------------------------------------------------------------------
#define ASTR 36
#define STAGES 3
#define GEMM_SMEM (STAGES * 128 * ASTR * 2 * 4)   // 110,592 B

template <int MODE>
__global__ void __launch_bounds__(256, 2)
gemm_tf32(float* __restrict__ Cp, int M, int N, int K)
{
    extern __shared__ unsigned gsm[];
    unsigned* As = gsm;                         // [STAGES][128][ASTR]
    unsigned* Bs = gsm + STAGES * 128 * ASTR;   // [STAGES][128][ASTR]

    const float* A = (MODE == 0) ? g_x : g_y;
    const float* B = (MODE == 0) ? g_wa : g_wp;   // [N][K]

    const int bx = blockIdx.x;
    const int by = blockIdx.y;
    const int tid  = threadIdx.x;
    const int lane = tid & 31;
    const int warp = tid >> 5;
    const int wm = warp >> 1;
    const int wn = warp & 1;
    const int tig = lane & 3;
    const int grp = lane >> 2;

    // cp.async load indexing: BK=32 -> 8 float4 per row; 4 rows per thread pass
    const int l_row = tid >> 3;          // 0..31
    const int l_kc  = (tid & 7) * 4;     // 0..28

    const float* Abase = A + (size_t)(by * 128) * K;
    const float* Bbase = B + (size_t)(bx * 128) * K;

    // ldmatrix lane offsets
    const int g8 = lane >> 3;
    const int r8 = lane & 7;
    const int a_ro = (g8 & 1) * 8 + r8;
    const int a_co = (g8 >> 1) * 4;
    const int b_ro = (g8 >> 1) * 8 + r8;
    const int b_co = (g8 & 1) * 4;

    const unsigned asb = (unsigned)__cvta_generic_to_shared(As);
    const unsigned bsb = (unsigned)__cvta_generic_to_shared(Bs);

    float acc[2][8][4];
#pragma unroll
    for (int i = 0; i < 2; i++)
#pragma unroll
        for (int j = 0; j < 8; j++)
#pragma unroll
            for (int r = 0; r < 4; r++) acc[i][j][r] = 0.f;

    const int nk = K >> 5;   // K/32

    // pipeline prologue: stages 0,1
#pragma unroll
    for (int p = 0; p < STAGES - 1; p++) {
        const int k0 = p << 5;
#pragma unroll
        for (int rr = 0; rr < 4; rr++) {
            const int r = l_row + rr * 32;
            cpasync16(&As[((size_t)p * 128 + r) * ASTR + l_kc],
                      Abase + (size_t)r * K + k0 + l_kc);
            cpasync16(&Bs[((size_t)p * 128 + r) * ASTR + l_kc],
                      Bbase + (size_t)r * K + k0 + l_kc);
        }
        cpasync_commit();
    }

    for (int ks = 0; ks < nk; ks++) {
        const int s = ks % STAGES;
        cpasync_wait<STAGES - 2>();
        __syncthreads();

#pragma unroll
        for (int kk = 0; kk < 4; kk++) {
            const int kb = kk * 8;
            unsigned af[2][4], bf[8][2];
#pragma unroll
            for (int mt = 0; mt < 2; mt++) {
                unsigned addr = asb +
                    ((s*128 + wm*32 + mt*16 + a_ro) * ASTR + kb + a_co) * 4;
                ldsm4(af[mt], addr);
            }
#pragma unroll
            for (int ntp = 0; ntp < 4; ntp++) {
                unsigned bq[4];
                unsigned addr = bsb +
                    ((s*128 + wn*64 + ntp*16 + b_ro) * ASTR + kb + b_co) * 4;
                ldsm4(bq, addr);
                bf[2*ntp][0]   = bq[0]; bf[2*ntp][1]   = bq[1];
                bf[2*ntp+1][0] = bq[2]; bf[2*ntp+1][1] = bq[3];
            }
#pragma unroll
            for (int mt = 0; mt < 2; mt++)
#pragma unroll
                for (int nt = 0; nt < 8; nt++)
                    mma_tf32(acc[mt][nt], af[mt], bf[nt]);
        }

        if (ks + STAGES - 1 < nk) {
            const int so = (ks + STAGES - 1) % STAGES;
            const int k0 = (ks + STAGES - 1) << 5;
#pragma unroll
            for (int rr = 0; rr < 4; rr++) {
                const int r = l_row + rr * 32;
                cpasync16(&As[((size_t)so * 128 + r) * ASTR + l_kc],
                          Abase + (size_t)r * K + k0 + l_kc);
                cpasync16(&Bs[((size_t)so * 128 + r) * ASTR + l_kc],
                          Bbase + (size_t)r * K + k0 + l_kc);
            }
        }
        cpasync_commit();
    }

    // epilogue
#pragma unroll
    for (int mt = 0; mt < 2; mt++) {
        const int row0 = by * 128 + wm * 32 + mt * 16 + grp;
#pragma unroll
        for (int nt = 0; nt < 8; nt++) {
            const int col = bx * 128 + wn * 64 + nt * 8 + tig * 2;
            if (MODE == 0) {
#pragma unroll
                for (int half = 0; half < 2; half++) {
                    const int row = row0 + half * 8;
                    const int bb = row >> 11;
                    const int t  = row & 2047;
                    const int which = col >> 11;
                    const int c = col & 2047;
                    const int h = c >> 7;
                    const int dd = c & 127;
                    float* base = (which == 0) ? g_q : (which == 1) ? g_k : g_v;
                    float* dst = base + ((size_t)(bb * NH + h) * TT + t) * HD + dd;
                    float v0 = acc[mt][nt][half * 2];
                    float v1 = acc[mt][nt][half * 2 + 1];
                    if (which == 2) { v0 = f2tf_f(v0); v1 = f2tf_f(v1); }
                    *(float2*)dst = make_float2(v0, v1);
                }
            } else {
                *(float2*)(Cp + (size_t)row0 * N + col) =
                    make_float2(acc[mt][nt][0], acc[mt][nt][1]);
                *(float2*)(Cp + (size_t)(row0 + 8) * N + col) =
                    make_float2(acc[mt][nt][2], acc[mt][nt][3]);
            }
        }
    }
}

// ---------------------------------------------------------------------------
// RoPE: rotate q,k in place, pre-round to tf32.
// q additionally scaled by (1/sqrt(hd))*log2(e) for log2-domain softmax.
// ---------------------------------------------------------------------------
#define QSCALE (0.08838834764831845f * 1.4426950408889634f)

__global__ void rope_kernel(const float* __restrict__ cosp,
                            const float* __restrict__ sinp)
{
    int row = blockIdx.x;
    int t = row & (TT - 1);
    int tid = threadIdx.x;
    int d = tid & 63;
    bool isq = (tid < 64);
    float* arr = isq ? g_q : g_k;
    float sc = isq ? QSCALE : 1.f;
    float* base = arr + (size_t)row * HD;
    float c = cosp[t*64 + d];
    float s = sinp[t*64 + d];
    float x1 = base[d];
    float x2 = base[d + 64];
    base[d]      = f2tf_f((x1*c - x2*s) * sc);
    base[d + 64] = f2tf_f((x1*s + x2*c) * sc);
}

// ---------------------------------------------------------------------------
// Flash attention v3: Q fragments in registers; K/V double-buffered cp.async;
// K fragments via ldmatrix; log2-domain ex2 softmax.
// Br=128 (8 warps x 16 rows), Bc=64.
// ---------------------------------------------------------------------------
#define FBR 128
#define FBC 64
#define FKS 132
#define FPS 68
#define KVW (2*FBC*FKS)                              // words per KV stage
#define FLASH3_SMEM ((2*KVW + 8*16*FPS) * 4)         // 169,984 B

__global__ void __launch_bounds__(256)
flash3_kernel()
{
    extern __shared__ unsigned sm[];
    unsigned* uKV = sm;                 // [2][K(64x132) | V(64x132)]
    unsigned* uP  = sm + 2*KVW;         // [8][16][FPS]

    const int qt  = blockIdx.x;
    const int bh  = blockIdx.y;
    const int tid = threadIdx.x;
    const int lane = tid & 31;
    const int wq   = tid >> 5;
    const int tig  = lane & 3;
    const int grp  = lane >> 2;
    const int g8 = lane >> 3;
    const int r8 = lane & 7;
    const int b_ro = (g8 >> 1) * 8 + r8;
    const int b_co = (g8 & 1) * 4;

    const unsigned kvb = (unsigned)__cvta_generic_to_shared(uKV);

    // ---- Q fragments straight from gmem into registers (tf32 bits) ----
    unsigned qf[16][4];
    {
        const unsigned* Qg = (const unsigned*)g_q + ((size_t)bh*TT + qt*FBR)*HD;
        const int r0 = (wq*16 + grp) * HD;
        const int r1 = (wq*16 + grp + 8) * HD;
#pragma unroll
        for (int ks = 0; ks < 16; ks++) {
            const int d0 = ks * 8;
            qf[ks][0] = Qg[r0 + d0 + tig];
            qf[ks][1] = Qg[r1 + d0 + tig];
            qf[ks][2] = Qg[r0 + d0 + tig + 4];
            qf[ks][3] = Qg[r1 + d0 + tig + 4];
        }
    }

    float m_i[2], l_i[2];
    m_i[0] = m_i[1] = -1e30f;
    l_i[0] = l_i[1] = 0.f;
    float oc[16][4];
#pragma unroll
    for (int n = 0; n < 16; n++)
#pragma unroll
        for (int r = 0; r < 4; r++) oc[n][r] = 0.f;

    const int warp_row0 = qt*FBR + wq*16;
    const int nblocks = 2*qt + 2;

    // K/V stage loader
    const float* Kall = g_k + (size_t)bh*TT*HD;
    const float* Vall = g_v + (size_t)bh*TT*HD;
#define ISSUE_KV(JC, ST)                                                       \
    {                                                                          \
        const float* Kg = Kall + (size_t)(JC)*FBC*HD;                          \
        const float* Vg = Vall + (size_t)(JC)*FBC*HD;                          \
        unsigned* dK = uKV + (ST)*KVW;                                         \
        unsigned* dV = dK + FBC*FKS;                                           \
        _Pragma("unroll")                                                      \
        for (int i = 0; i < 8; i++) {                                          \
            int lin = tid + i*256;                                             \
            int r  = lin >> 5;                                                 \
            int c4 = (lin & 31) * 4;                                           \
            cpasync16(&dK[r*FKS + c4], Kg + (size_t)r*HD + c4);                \
            cpasync16(&dV[r*FKS + c4], Vg + (size_t)r*HD + c4);                \
        }                                                                      \
    }

    ISSUE_KV(0, 0);
    cpasync_commit();

    for (int jc = 0; jc < nblocks; jc++) {
        const int s = jc & 1;
        cpasync_wait<0>();
        __syncthreads();   // all warps done with the other stage + data visible
        if (jc + 1 < nblocks) {
            ISSUE_KV(jc + 1, s ^ 1);
            cpasync_commit();
        }

        if (jc*FBC > warp_row0 + 15) continue;
        const bool diag = (jc*FBC + FBC - 1) > warp_row0;

        unsigned* uV = uKV + s*KVW + FBC*FKS;
        const unsigned kbase = kvb + (unsigned)(s*KVW) * 4;

        // ---- S = Q K^T (log2 units) ----
        float sc[8][4];
#pragma unroll
        for (int n = 0; n < 8; n++)
#pragma unroll
            for (int r = 0; r < 4; r++) sc[n][r] = 0.f;

#pragma unroll
        for (int ks = 0; ks < 16; ks++) {
            const int d0 = ks*8;
            unsigned bf[8][2];
#pragma unroll
            for (int ntp = 0; ntp < 4; ntp++) {
                unsigned bq[4];
                unsigned addr = kbase + ((ntp*16 + b_ro)*FKS + d0 + b_co) * 4;
                ldsm4(bq, addr);
                bf[2*ntp][0]   = bq[0]; bf[2*ntp][1]   = bq[1];
                bf[2*ntp+1][0] = bq[2]; bf[2*ntp+1][1] = bq[3];
            }
#pragma unroll
            for (int nt = 0; nt < 8; nt++)
                mma_tf32(sc[nt], qf[ks], bf[nt]);
        }

        // ---- online softmax (log2 domain) ----
        unsigned* Pw = uP + wq*16*FPS;
#pragma unroll
        for (int h = 0; h < 2; h++) {
            const int row = warp_row0 + grp + h*8;
            float rmax = -1e30f;
            if (diag) {
#pragma unroll
                for (int nt = 0; nt < 8; nt++)
#pragma unroll
                    for (int c = 0; c < 2; c++) {
                        const int col = jc*FBC + nt*8 + tig*2 + c;
                        float v = sc[nt][h*2 + c];
                        if (col > row) v = -1e30f;
                        sc[nt][h*2 + c] = v;
                        rmax = fmaxf(rmax, v);
                    }
            } else {
#pragma unroll
                for (int nt = 0; nt < 8; nt++)
                    rmax = fmaxf(rmax, fmaxf(sc[nt][h*2], sc[nt][h*2 + 1]));
            }
            rmax = fmaxf(rmax, __shfl_xor_sync(0xffffffffu, rmax, 1));
            rmax = fmaxf(rmax, __shfl_xor_sync(0xffffffffu, rmax, 2));

            const float m_new = fmaxf(m_i[h], rmax);
            const float fac = ex2(m_i[h] - m_new);
            float rsum = 0.f;
#pragma unroll
            for (int nt = 0; nt < 8; nt++) {
#pragma unroll
                for (int c = 0; c < 2; c++) {
                    float p = ex2(sc[nt][h*2 + c] - m_new);
                    rsum += p;
                    Pw[(grp + h*8)*FPS + nt*8 + tig*2 + c] = f2tf(p);
                }
            }
            rsum += __shfl_xor_sync(0xffffffffu, rsum, 1);
            rsum += __shfl_xor_sync(0xffffffffu, rsum, 2);

            l_i[h] = l_i[h]*fac + rsum;
            m_i[h] = m_new;
#pragma unroll
            for (int nt = 0; nt < 16; nt++) {
                oc[nt][h*2]     *= fac;
                oc[nt][h*2 + 1] *= fac;
            }
        }
        __syncwarp();

        // ---- O += P V ----
#pragma unroll
        for (int k0 = 0; k0 < FBC; k0 += 8) {
            unsigned af[4];
            af[0] = Pw[(grp    )*FPS + k0 + tig];
            af[1] = Pw[(grp + 8)*FPS + k0 + tig];
            af[2] = Pw[(grp    )*FPS + k0 + tig + 4];
            af[3] = Pw[(grp + 8)*FPS + k0 + tig + 4];
#pragma unroll
            for (int nt = 0; nt < 16; nt++) {
                unsigned bf[2];
                bf[0] = uV[(k0 + tig    )*FKS + nt*8 + grp];
                bf[1] = uV[(k0 + tig + 4)*FKS + nt*8 + grp];
                mma_tf32(oc[nt], af, bf);
            }
        }
    }

    // epilogue: y pre-rounded for gemm<1>
    const int b = bh >> 4;
    const int h = bh & 15;
#pragma unroll
    for (int hh = 0; hh < 2; hh++) {
        const int t = qt*FBR + wq*16 + grp + hh*8;
        const float inv = 1.f / l_i[hh];
        float* yrow = g_y + ((size_t)(b*TT + t))*CC + h*HD;
#pragma unroll
        for (int nt = 0; nt < 16; nt++) {
            *(float2*)(yrow + nt*8 + tig*2) =
                make_float2(f2tf_f(oc[nt][hh*2] * inv),
                            f2tf_f(oc[nt][hh*2 + 1] * inv));
        }
    }
}

// ---------------------------------------------------------------------------
// launch
// ---------------------------------------------------------------------------
extern "C" void kernel_launch(void* const* d_in, const int* in_sizes, int n_in,
                              void* d_out, int out_size)
{
    const float* x    = (const float*)d_in[0];
    const float* cosp = (const float*)d_in[1];
    const float* sinp = (const float*)d_in[2];
    const float* Wa   = (const float*)d_in[3];
    const float* Wp   = (const float*)d_in[4];
    float* out = (float*)d_out;

    float *dx, *dwa, *dwp;
    cudaGetSymbolAddress((void**)&dx,  g_x);
    cudaGetSymbolAddress((void**)&dwa, g_wa);
    cudaGetSymbolAddress((void**)&dwp, g_wp);

    // 0) pre-round x; transpose + pre-round weights
    cvt_tf32_kernel<<<2048, 256>>>((const float4*)x, (float4*)dx, MM*CC/4);
    cvt_t_kernel<<<dim3(N_QKV/32, CC/32), dim3(32, 8)>>>(Wa, dwa, CC, N_QKV);
    cvt_t_kernel<<<dim3(CC/32,   CC/32), dim3(32, 8)>>>(Wp, dwp, CC, CC);

    // 1) qkv = x @ W_attn -> head-major q/k/v
    cudaFuncSetAttribute(gemm_tf32<0>, cudaFuncAttributeMaxDynamicSharedMemorySize,
                         GEMM_SMEM);
    gemm_tf32<0><<<dim3(N_QKV/128, MM/128), 256, GEMM_SMEM>>>(nullptr, MM, N_QKV, CC);

    // 2) RoPE on q,k (q pre-scaled by 1/sqrt(hd)*log2e, tf32-rounded)
    rope_kernel<<<BB*NH*TT, 128>>>(cosp, sinp);

    // 3) flash attention -> g_y (tf32-rounded)
    cudaFuncSetAttribute(flash3_kernel, cudaFuncAttributeMaxDynamicSharedMemorySize,
                         FLASH3_SMEM);
    flash3_kernel<<<dim3(TT/FBR, BB*NH), 256, FLASH3_SMEM>>>();

    // 4) out = y @ W_proj
    cudaFuncSetAttribute(gemm_tf32<1>, cudaFuncAttributeMaxDynamicSharedMemorySize,
                         GEMM_SMEM);
    gemm_tf32<1><<<dim3(CC/128, MM/128), 256, GEMM_SMEM>>>(out, MM, CC, CC);
}

// round 10
// speedup vs baseline: 7.8374x; 1.0471x over previous
#include <cuda_runtime.h>
#include <cuda_bf16.h>
#include <math.h>

// Problem constants
#define BB   2
#define TT   2048
#define CC   2048
#define NH   16
#define HD   128
#define MM   (BB*TT)        // 4096
#define N_QKV (3*CC)        // 6144

// ---------------------------------------------------------------------------
// Scratch (device globals; no runtime allocation)
// ---------------------------------------------------------------------------
__device__ float g_q[(size_t)BB*NH*TT*HD];   // [B,H,T,hd], q pre-scaled, tf32 bits
__device__ float g_k[(size_t)BB*NH*TT*HD];   // [B,H,T,hd], tf32 bits
__device__ float g_vt[(size_t)BB*NH*HD*TT];  // [B,H,hd,T]  V TRANSPOSED, tf32 bits
__device__ float g_y[(size_t)BB*TT*CC];      // tf32 bits
__device__ float g_x[(size_t)MM*CC];         // tf32 bits
__device__ float g_wa[(size_t)CC*N_QKV];     // tf32 bits, W_attn^T [N_QKV][CC]
__device__ float g_wp[(size_t)CC*CC];        // tf32 bits, W_proj^T [CC][CC]

// ---------------------------------------------------------------------------
// TF32 / math helpers
// ---------------------------------------------------------------------------
__device__ __forceinline__ unsigned f2tf(float x) {
    unsigned r;
    asm("cvt.rna.tf32.f32 %0, %1;" : "=r"(r) : "f"(x));
    return r;
}
__device__ __forceinline__ float f2tf_f(float x) {
    return __uint_as_float(f2tf(x));
}
__device__ __forceinline__ float ex2(float x) {
    float y;
    asm("ex2.approx.f32 %0, %1;" : "=f"(y) : "f"(x));
    return y;
}

__device__ __forceinline__ void mma_tf32(float* c, const unsigned* a, const unsigned* b) {
    asm volatile(
        "mma.sync.aligned.m16n8k8.row.col.f32.tf32.tf32.f32 "
        "{%0,%1,%2,%3}, {%4,%5,%6,%7}, {%8,%9}, {%0,%1,%2,%3};"
        : "+f"(c[0]), "+f"(c[1]), "+f"(c[2]), "+f"(c[3])
        : "r"(a[0]), "r"(a[1]), "r"(a[2]), "r"(a[3]),
          "r"(b[0]), "r"(b[1]));
}

__device__ __forceinline__ void ldsm4(unsigned* r, unsigned addr) {
    asm volatile("ldmatrix.sync.aligned.m8n8.x4.shared.b16 {%0,%1,%2,%3}, [%4];"
        : "=r"(r[0]), "=r"(r[1]), "=r"(r[2]), "=r"(r[3]) : "r"(addr));
}

// cp.async helpers
__device__ __forceinline__ void cpasync16(void* smem_dst, const void* gsrc) {
    unsigned s = (unsigned)__cvta_generic_to_shared(smem_dst);
    asm volatile("cp.async.cg.shared.global [%0], [%1], 16;\n" :: "r"(s), "l"(gsrc));
}
__device__ __forceinline__ void cpasync_commit() {
    asm volatile("cp.async.commit_group;\n");
}
template <int N>
__device__ __forceinline__ void cpasync_wait() {
    asm volatile("cp.async.wait_group %0;\n" :: "n"(N));
}

// ---------------------------------------------------------------------------
// Pre-round fp32 -> tf32 bits (elementwise, float4 grid-stride) — for x
// ---------------------------------------------------------------------------
__global__ void cvt_tf32_kernel(const float4* __restrict__ in,
                                float4* __restrict__ out, int n4)
{
    for (int i = blockIdx.x * blockDim.x + threadIdx.x; i < n4;
         i += gridDim.x * blockDim.x) {
        float4 v = in[i];
        v.x = f2tf_f(v.x); v.y = f2tf_f(v.y); v.z = f2tf_f(v.z); v.w = f2tf_f(v.w);
        out[i] = v;
    }
}

// ---------------------------------------------------------------------------
// Transpose + pre-round: out[n][k] = tf32(in[k][n]).  in: [K][N]
// ---------------------------------------------------------------------------
__global__ void cvt_t_kernel(const float* __restrict__ in,
                             float* __restrict__ out, int K, int N)
{
    __shared__ float tile[32][33];
    const int k0 = blockIdx.y * 32;
    const int n0 = blockIdx.x * 32;
#pragma unroll
    for (int i = threadIdx.y; i < 32; i += 8)
        tile[i][threadIdx.x] = in[(size_t)(k0 + i) * N + n0 + threadIdx.x];
    __syncthreads();
#pragma unroll
    for (int i = threadIdx.y; i < 32; i += 8)
        out[(size_t)(n0 + i) * K + k0 + threadIdx.x] = f2tf_f(tile[threadIdx.x][i]);
}

// ---------------------------------------------------------------------------
// TF32 GEMM, B pre-transposed.  C = A[M,K] @ B'[N,K]^T
// 128x128 tile, BK=32, cp.async 3-stage, 2 CTAs/SM, ldmatrix fragment loads.
// MODE 0: A=g_x, B=g_wa, epilogue scatters into g_q/g_k/g_vt (V transposed!)
// MODE 1: A=g_y, B=g_wp, epilogue writes row-major C (d_out)
// ---------------------------------------------------------------------------
#define ASTR 36
#define STAGES 3
#define GEMM_SMEM (STAGES * 128 * ASTR * 2 * 4)   // 110,592 B

template <int MODE>
__global__ void __launch_bounds__(256, 2)
gemm_tf32(float* __restrict__ Cp, int M, int N, int K)
{
    extern __shared__ unsigned gsm[];
    unsigned* As = gsm;                         // [STAGES][128][ASTR]
    unsigned* Bs = gsm + STAGES * 128 * ASTR;   // [STAGES][128][ASTR]

    const float* A = (MODE == 0) ? g_x : g_y;
    const float* B = (MODE == 0) ? g_wa : g_wp;   // [N][K]

    const int bx = blockIdx.x;
    const int by = blockIdx.y;
    const int tid  = threadIdx.x;
    const int lane = tid & 31;
    const int warp = tid >> 5;
    const int wm = warp >> 1;
    const int wn = warp & 1;
    const int tig = lane & 3;
    const int grp = lane >> 2;

    const int l_row = tid >> 3;          // 0..31
    const int l_kc  = (tid & 7) * 4;     // 0..28

    const float* Abase = A + (size_t)(by * 128) * K;
    const float* Bbase = B + (size_t)(bx * 128) * K;

    const int g8 = lane >> 3;
    const int r8 = lane & 7;
    const int a_ro = (g8 & 1) * 8 + r8;
    const int a_co = (g8 >> 1) * 4;
    const int b_ro = (g8 >> 1) * 8 + r8;
    const int b_co = (g8 & 1) * 4;

    const unsigned asb = (unsigned)__cvta_generic_to_shared(As);
    const unsigned bsb = (unsigned)__cvta_generic_to_shared(Bs);

    float acc[2][8][4];
#pragma unroll
    for (int i = 0; i < 2; i++)
#pragma unroll
        for (int j = 0; j < 8; j++)
#pragma unroll
            for (int r = 0; r < 4; r++) acc[i][j][r] = 0.f;

    const int nk = K >> 5;   // K/32

#pragma unroll
    for (int p = 0; p < STAGES - 1; p++) {
        const int k0 = p << 5;
#pragma unroll
        for (int rr = 0; rr < 4; rr++) {
            const int r = l_row + rr * 32;
            cpasync16(&As[((size_t)p * 128 + r) * ASTR + l_kc],
                      Abase + (size_t)r * K + k0 + l_kc);
            cpasync16(&Bs[((size_t)p * 128 + r) * ASTR + l_kc],
                      Bbase + (size_t)r * K + k0 + l_kc);
        }
        cpasync_commit();
    }

    for (int ks = 0; ks < nk; ks++) {
        const int s = ks % STAGES;
        cpasync_wait<STAGES - 2>();
        __syncthreads();

#pragma unroll
        for (int kk = 0; kk < 4; kk++) {
            const int kb = kk * 8;
            unsigned af[2][4], bf[8][2];
#pragma unroll
            for (int mt = 0; mt < 2; mt++) {
                unsigned addr = asb +
                    ((s*128 + wm*32 + mt*16 + a_ro) * ASTR + kb + a_co) * 4;
                ldsm4(af[mt], addr);
            }
#pragma unroll
            for (int ntp = 0; ntp < 4; ntp++) {
                unsigned bq[4];
                unsigned addr = bsb +
                    ((s*128 + wn*64 + ntp*16 + b_ro) * ASTR + kb + b_co) * 4;
                ldsm4(bq, addr);
                bf[2*ntp][0]   = bq[0]; bf[2*ntp][1]   = bq[1];
                bf[2*ntp+1][0] = bq[2]; bf[2*ntp+1][1] = bq[3];
            }
#pragma unroll
            for (int mt = 0; mt < 2; mt++)
#pragma unroll
                for (int nt = 0; nt < 8; nt++)
                    mma_tf32(acc[mt][nt], af[mt], bf[nt]);
        }

        if (ks + STAGES - 1 < nk) {
            const int so = (ks + STAGES - 1) % STAGES;
            const int k0 = (ks + STAGES - 1) << 5;
#pragma unroll
            for (int rr = 0; rr < 4; rr++) {
                const int r = l_row + rr * 32;
                cpasync16(&As[((size_t)so * 128 + r) * ASTR + l_kc],
                          Abase + (size_t)r * K + k0 + l_kc);
                cpasync16(&Bs[((size_t)so * 128 + r) * ASTR + l_kc],
                          Bbase + (size_t)r * K + k0 + l_kc);
            }
        }
        cpasync_commit();
    }

    // epilogue
#pragma unroll
    for (int mt = 0; mt < 2; mt++) {
        const int row0 = by * 128 + wm * 32 + mt * 16 + grp;
#pragma unroll
        for (int nt = 0; nt < 8; nt++) {
            const int col = bx * 128 + wn * 64 + nt * 8 + tig * 2;
            if (MODE == 0) {
#pragma unroll
                for (int half = 0; half < 2; half++) {
                    const int row = row0 + half * 8;
                    const int bb = row >> 11;
                    const int t  = row & 2047;
                    const int which = col >> 11;
                    const int c = col & 2047;
                    const int h = c >> 7;
                    const int dd = c & 127;
                    float v0 = acc[mt][nt][half * 2];
                    float v1 = acc[mt][nt][half * 2 + 1];
                    if (which == 2) {
                        // V transposed: g_vt[(bh*HD + dd)*TT + t]
                        float* dst = g_vt + ((size_t)((bb*NH + h)*HD + dd))*TT + t;
                        dst[0]  = f2tf_f(v0);
                        dst[TT] = f2tf_f(v1);
                    } else {
                        float* base = (which == 0) ? g_q : g_k;
                        float* dst = base + ((size_t)(bb*NH + h)*TT + t)*HD + dd;
                        *(float2*)dst = make_float2(v0, v1);
                    }
                }
            } else {
                *(float2*)(Cp + (size_t)row0 * N + col) =
                    make_float2(acc[mt][nt][0], acc[mt][nt][1]);
                *(float2*)(Cp + (size_t)(row0 + 8) * N + col) =
                    make_float2(acc[mt][nt][2], acc[mt][nt][3]);
            }
        }
    }
}

// ---------------------------------------------------------------------------
// RoPE: rotate q,k in place, pre-round to tf32.
// q additionally scaled by (1/sqrt(hd))*log2(e) for log2-domain softmax.
// ---------------------------------------------------------------------------
#define QSCALE (0.08838834764831845f * 1.4426950408889634f)

__global__ void rope_kernel(const float* __restrict__ cosp,
                            const float* __restrict__ sinp)
{
    int row = blockIdx.x;
    int t = row & (TT - 1);
    int tid = threadIdx.x;
    int d = tid & 63;
    bool isq = (tid < 64);
    float* arr = isq ? g_q : g_k;
    float sc = isq ? QSCALE : 1.f;
    float* base = arr + (size_t)row * HD;
    float c = cosp[t*64 + d];
    float s = sinp[t*64 + d];
    float x1 = base[d];
    float x2 = base[d + 64];
    base[d]      = f2tf_f((x1*c - x2*s) * sc);
    base[d + 64] = f2tf_f((x1*s + x2*c) * sc);
}

// ---------------------------------------------------------------------------
// Flash attention v4: Q fragments in registers; K + V^T double-buffered
// cp.async; K AND V fragments via ldmatrix; log2-domain ex2 softmax.
// Br=128 (8 warps x 16 rows), Bc=64.
// ---------------------------------------------------------------------------
#define FBR 128
#define FBC 64
#define FKS 132                       // K tile row stride (words), 64 rows
#define VTS 68                        // V^T tile row stride (words), 128 rows
#define FPS 68
#define STW (FBC*FKS + HD*VTS)        // words per stage: K + V^T = 17152
#define FLASH4_SMEM ((2*STW + 8*16*FPS) * 4)   // 172,032 B

__global__ void __launch_bounds__(256)
flash4_kernel()
{
    extern __shared__ unsigned sm[];
    unsigned* uP = sm + 2*STW;

    const int qt  = blockIdx.x;
    const int bh  = blockIdx.y;
    const int tid = threadIdx.x;
    const int lane = tid & 31;
    const int wq   = tid >> 5;
    const int tig  = lane & 3;
    const int grp  = lane >> 2;
    const int g8 = lane >> 3;
    const int r8 = lane & 7;
    const int b_ro = (g8 >> 1) * 8 + r8;
    const int b_co = (g8 & 1) * 4;

    const unsigned smb = (unsigned)__cvta_generic_to_shared(sm);

    // ---- Q fragments straight from gmem into registers (tf32 bits) ----
    unsigned qf[16][4];
    {
        const unsigned* Qg = (const unsigned*)g_q + ((size_t)bh*TT + qt*FBR)*HD;
        const int r0 = (wq*16 + grp) * HD;
        const int r1 = (wq*16 + grp + 8) * HD;
#pragma unroll
        for (int ks = 0; ks < 16; ks++) {
            const int d0 = ks * 8;
            qf[ks][0] = Qg[r0 + d0 + tig];
            qf[ks][1] = Qg[r1 + d0 + tig];
            qf[ks][2] = Qg[r0 + d0 + tig + 4];
            qf[ks][3] = Qg[r1 + d0 + tig + 4];
        }
    }

    float m_i[2], l_i[2];
    m_i[0] = m_i[1] = -1e30f;
    l_i[0] = l_i[1] = 0.f;
    float oc[16][4];
#pragma unroll
    for (int n = 0; n < 16; n++)
#pragma unroll
        for (int r = 0; r < 4; r++) oc[n][r] = 0.f;

    const int warp_row0 = qt*FBR + wq*16;
    const int nblocks = 2*qt + 2;

    const float* Kall  = g_k  + (size_t)bh*TT*HD;
    const float* Vtall = g_vt + (size_t)bh*HD*TT;

    // stage loader: K tile [64 tok][128 hd], V^T tile [128 hd][64 tok]
#define ISSUE_KV(JC, ST)                                                       \
    {                                                                          \
        const float* Kg  = Kall  + (size_t)(JC)*FBC*HD;                        \
        const float* Vtg = Vtall + (JC)*FBC;                                   \
        unsigned* dK = sm + (ST)*STW;                                          \
        unsigned* dV = dK + FBC*FKS;                                           \
        _Pragma("unroll")                                                      \
        for (int i = 0; i < 8; i++) {                                          \
            int lin = tid + i*256;                                             \
            int r  = lin >> 5;                                                 \
            int c4 = (lin & 31) * 4;                                           \
            cpasync16(&dK[r*FKS + c4], Kg + (size_t)r*HD + c4);                \
        }                                                                      \
        _Pragma("unroll")                                                      \
        for (int i = 0; i < 8; i++) {                                          \
            int lin = tid + i*256;                                             \
            int r  = lin >> 4;            /* 0..127 hd row */                  \
            int c4 = (lin & 15) * 4;      /* 0..60 token col */                \
            cpasync16(&dV[r*VTS + c4], Vtg + (size_t)r*TT + c4);               \
        }                                                                      \
    }

    ISSUE_KV(0, 0);
    cpasync_commit();

    for (int jc = 0; jc < nblocks; jc++) {
        const int s = jc & 1;
        cpasync_wait<0>();
        __syncthreads();
        if (jc + 1 < nblocks) {
            ISSUE_KV(jc + 1, s ^ 1);
            cpasync_commit();
        }

        if (jc*FBC > warp_row0 + 15) continue;
        const bool diag = (jc*FBC + FBC - 1) > warp_row0;

        const unsigned kbase = smb + (unsigned)(s*STW) * 4;
        const unsigned vbase = smb + (unsigned)(s*STW + FBC*FKS) * 4;

        // ---- S = Q K^T (log2 units) ----
        float sc[8][4];
#pragma unroll
        for (int n = 0; n < 8; n++)
#pragma unroll
            for (int r = 0; r < 4; r++) sc[n][r] = 0.f;

#pragma unroll
        for (int ks = 0; ks < 16; ks++) {
            const int d0 = ks*8;
            unsigned bf[8][2];
#pragma unroll
            for (int ntp = 0; ntp < 4; ntp++) {
                unsigned bq[4];
                unsigned addr = kbase + ((ntp*16 + b_ro)*FKS + d0 + b_co) * 4;
                ldsm4(bq, addr);
                bf[2*ntp][0]   = bq[0]; bf[2*ntp][1]   = bq[1];
                bf[2*ntp+1][0] = bq[2]; bf[2*ntp+1][1] = bq[3];
            }
#pragma unroll
            for (int nt = 0; nt < 8; nt++)
                mma_tf32(sc[nt], qf[ks], bf[nt]);
        }

        // ---- online softmax (log2 domain) ----
        unsigned* Pw = uP + wq*16*FPS;
#pragma unroll
        for (int h = 0; h < 2; h++) {
            const int row = warp_row0 + grp + h*8;
            float rmax = -1e30f;
            if (diag) {
#pragma unroll
                for (int nt = 0; nt < 8; nt++)
#pragma unroll
                    for (int c = 0; c < 2; c++) {
                        const int col = jc*FBC + nt*8 + tig*2 + c;
                        float v = sc[nt][h*2 + c];
                        if (col > row) v = -1e30f;
                        sc[nt][h*2 + c] = v;
                        rmax = fmaxf(rmax, v);
                    }
            } else {
#pragma unroll
                for (int nt = 0; nt < 8; nt++)
                    rmax = fmaxf(rmax, fmaxf(sc[nt][h*2], sc[nt][h*2 + 1]));
            }
            rmax = fmaxf(rmax, __shfl_xor_sync(0xffffffffu, rmax, 1));
            rmax = fmaxf(rmax, __shfl_xor_sync(0xffffffffu, rmax, 2));

            const float m_new = fmaxf(m_i[h], rmax);
            const float fac = ex2(m_i[h] - m_new);
            float rsum = 0.f;
#pragma unroll
            for (int nt = 0; nt < 8; nt++) {
#pragma unroll
                for (int c = 0; c < 2; c++) {
                    float p = ex2(sc[nt][h*2 + c] - m_new);
                    rsum += p;
                    Pw[(grp + h*8)*FPS + nt*8 + tig*2 + c] = f2tf(p);
                }
            }
            rsum += __shfl_xor_sync(0xffffffffu, rsum, 1);
            rsum += __shfl_xor_sync(0xffffffffu, rsum, 2);

            l_i[h] = l_i[h]*fac + rsum;
            m_i[h] = m_new;
#pragma unroll
            for (int nt = 0; nt < 16; nt++) {
                oc[nt][h*2]     *= fac;
                oc[nt][h*2 + 1] *= fac;
            }
        }
        __syncwarp();

        // ---- O += P V  (V fragments via ldmatrix on V^T) ----
#pragma unroll
        for (int k0 = 0; k0 < FBC; k0 += 8) {
            unsigned af[4];
            af[0] = Pw[(grp    )*FPS + k0 + tig];
            af[1] = Pw[(grp + 8)*FPS + k0 + tig];
            af[2] = Pw[(grp    )*FPS + k0 + tig + 4];
            af[3] = Pw[(grp + 8)*FPS + k0 + tig + 4];
#pragma unroll
            for (int np = 0; np < 8; np++) {
                unsigned bq[4];
                unsigned addr = vbase + ((np*16 + b_ro)*VTS + k0 + b_co) * 4;
                ldsm4(bq, addr);
                unsigned bf0[2] = {bq[0], bq[1]};
                unsigned bf1[2] = {bq[2], bq[3]};
                mma_tf32(oc[2*np],     af, bf0);
                mma_tf32(oc[2*np + 1], af, bf1);
            }
        }
    }

    // epilogue: y pre-rounded for gemm<1>
    const int b = bh >> 4;
    const int h = bh & 15;
#pragma unroll
    for (int hh = 0; hh < 2; hh++) {
        const int t = qt*FBR + wq*16 + grp + hh*8;
        const float inv = 1.f / l_i[hh];
        float* yrow = g_y + ((size_t)(b*TT + t))*CC + h*HD;
#pragma unroll
        for (int nt = 0; nt < 16; nt++) {
            *(float2*)(yrow + nt*8 + tig*2) =
                make_float2(f2tf_f(oc[nt][hh*2] * inv),
                            f2tf_f(oc[nt][hh*2 + 1] * inv));
        }
    }
}

// ---------------------------------------------------------------------------
// launch
// ---------------------------------------------------------------------------
extern "C" void kernel_launch(void* const* d_in, const int* in_sizes, int n_in,
                              void* d_out, int out_size)
{
    const float* x    = (const float*)d_in[0];
    const float* cosp = (const float*)d_in[1];
    const float* sinp = (const float*)d_in[2];
    const float* Wa   = (const float*)d_in[3];
    const float* Wp   = (const float*)d_in[4];
    float* out = (float*)d_out;

    float *dx, *dwa, *dwp;
    cudaGetSymbolAddress((void**)&dx,  g_x);
    cudaGetSymbolAddress((void**)&dwa, g_wa);
    cudaGetSymbolAddress((void**)&dwp, g_wp);

    // 0) pre-round x; transpose + pre-round weights
    cvt_tf32_kernel<<<2048, 256>>>((const float4*)x, (float4*)dx, MM*CC/4);
    cvt_t_kernel<<<dim3(N_QKV/32, CC/32), dim3(32, 8)>>>(Wa, dwa, CC, N_QKV);
    cvt_t_kernel<<<dim3(CC/32,   CC/32), dim3(32, 8)>>>(Wp, dwp, CC, CC);

    // 1) qkv = x @ W_attn -> head-major q/k + transposed v
    cudaFuncSetAttribute(gemm_tf32<0>, cudaFuncAttributeMaxDynamicSharedMemorySize,
                         GEMM_SMEM);
    gemm_tf32<0><<<dim3(N_QKV/128, MM/128), 256, GEMM_SMEM>>>(nullptr, MM, N_QKV, CC);

    // 2) RoPE on q,k
    rope_kernel<<<BB*NH*TT, 128>>>(cosp, sinp);

    // 3) flash attention -> g_y
    cudaFuncSetAttribute(flash4_kernel, cudaFuncAttributeMaxDynamicSharedMemorySize,
                         FLASH4_SMEM);
    flash4_kernel<<<dim3(TT/FBR, BB*NH), 256, FLASH4_SMEM>>>();

    // 4) out = y @ W_proj
    cudaFuncSetAttribute(gemm_tf32<1>, cudaFuncAttributeMaxDynamicSharedMemorySize,
                         GEMM_SMEM);
    gemm_tf32<1><<<dim3(CC/128, MM/128), 256, GEMM_SMEM>>>(out, MM, CC, CC);
}